// round 10
// baseline (speedup 1.0000x reference)
#include <cuda_runtime.h>
#include <math_constants.h>

#define BB 2
#define HH 8
#define LL 2048
#define DD 64
#define CC 512
#define NQ 16
#define NK 32
#define BLKQ 128
#define BLKK 64

// ---------------- scratch (no allocations allowed) ----------------
__device__ float g_q[BB*HH*LL*DD];
__device__ float g_k[BB*HH*LL*DD];
__device__ float g_v[BB*HH*LL*DD];
__device__ float g_qm[BB*HH*NQ*DD];
__device__ float g_km[BB*HH*NK*DD];
__device__ float g_qsim[BB*HH*NQ];
__device__ float g_ksim[BB*HH*NK];
__device__ int   g_cnt[BB*HH*NQ];
__device__ int   g_list[BB*HH*NQ*NK];
__device__ float g_ot[BB*LL*CC];

__device__ __forceinline__ unsigned f2tf(float x) {
    unsigned r;
    asm("cvt.rna.tf32.f32 %0, %1;" : "=r"(r) : "f"(x));
    return r;
}
__device__ __forceinline__ float f2tff(float x) { return __uint_as_float(f2tf(x)); }

#define MMA_TF32(c, a0, a1, a2, a3, b0, b1)                                   \
    asm volatile(                                                             \
        "mma.sync.aligned.m16n8k8.row.col.f32.tf32.tf32.f32 "                 \
        "{%0,%1,%2,%3},{%4,%5,%6,%7},{%8,%9},{%0,%1,%2,%3};"                  \
        : "+f"((c)[0]), "+f"((c)[1]), "+f"((c)[2]), "+f"((c)[3])              \
        : "r"(a0), "r"(a1), "r"(a2), "r"(a3), "r"(b0), "r"(b1))

// ---------------- 3xTF32 tensor-core GEMM with register prefetch ----------------
template<int N, bool QKV>
__global__ void __launch_bounds__(128) gemm_tf32(const float* __restrict__ Ain,
                                                 const float* __restrict__ W,
                                                 const float* __restrict__ bias,
                                                 float* __restrict__ out) {
    __shared__ float Ah[64][36], Al[64][36];
    __shared__ float Bh[32][72], Bl[32][72];
    const float* __restrict__ A = QKV ? Ain : (const float*)g_ot;
    const int K = CC;
    int tid = threadIdx.x;
    int w = tid >> 5, lane = tid & 31;
    int g = lane >> 2, t = lane & 3;
    int wm = (w & 1) * 32, wn = (w >> 1) * 32;
    int m0 = blockIdx.y * 64, n0 = blockIdx.x * 64;

    int arow = tid >> 3, ac4 = (tid & 7) * 4;
    int brow = tid >> 4, bc4 = (tid & 15) * 4;

    float4 pa[4], pb[4];
    #pragma unroll
    for (int i = 0; i < 4; i++) {
        pa[i] = *(const float4*)&A[(m0 + arow + i * 16) * K + ac4];
        pb[i] = *(const float4*)&W[(brow + i * 8) * N + n0 + bc4];
    }

    float acc[2][4][4] = {};

    for (int k0 = 0; k0 < K; k0 += 32) {
        __syncthreads();
        #pragma unroll
        for (int i = 0; i < 4; i++) {
            float4 v = pa[i];
            int row = arow + i * 16;
            float h0 = f2tff(v.x), h1 = f2tff(v.y), h2 = f2tff(v.z), h3 = f2tff(v.w);
            Ah[row][ac4+0] = h0; Ah[row][ac4+1] = h1; Ah[row][ac4+2] = h2; Ah[row][ac4+3] = h3;
            Al[row][ac4+0] = f2tff(v.x - h0); Al[row][ac4+1] = f2tff(v.y - h1);
            Al[row][ac4+2] = f2tff(v.z - h2); Al[row][ac4+3] = f2tff(v.w - h3);
            v = pb[i];
            row = brow + i * 8;
            h0 = f2tff(v.x); h1 = f2tff(v.y); h2 = f2tff(v.z); h3 = f2tff(v.w);
            Bh[row][bc4+0] = h0; Bh[row][bc4+1] = h1; Bh[row][bc4+2] = h2; Bh[row][bc4+3] = h3;
            Bl[row][bc4+0] = f2tff(v.x - h0); Bl[row][bc4+1] = f2tff(v.y - h1);
            Bl[row][bc4+2] = f2tff(v.z - h2); Bl[row][bc4+3] = f2tff(v.w - h3);
        }
        __syncthreads();
        if (k0 + 32 < K) {
            #pragma unroll
            for (int i = 0; i < 4; i++) {
                pa[i] = *(const float4*)&A[(m0 + arow + i * 16) * K + k0 + 32 + ac4];
                pb[i] = *(const float4*)&W[(k0 + 32 + brow + i * 8) * N + n0 + bc4];
            }
        }
        #pragma unroll
        for (int kc = 0; kc < 4; kc++) {
            unsigned ah[2][4], al[2][4];
            #pragma unroll
            for (int mf = 0; mf < 2; mf++) {
                int r0 = wm + mf * 16 + g;
                ah[mf][0] = __float_as_uint(Ah[r0][kc*8+t]);
                ah[mf][1] = __float_as_uint(Ah[r0+8][kc*8+t]);
                ah[mf][2] = __float_as_uint(Ah[r0][kc*8+t+4]);
                ah[mf][3] = __float_as_uint(Ah[r0+8][kc*8+t+4]);
                al[mf][0] = __float_as_uint(Al[r0][kc*8+t]);
                al[mf][1] = __float_as_uint(Al[r0+8][kc*8+t]);
                al[mf][2] = __float_as_uint(Al[r0][kc*8+t+4]);
                al[mf][3] = __float_as_uint(Al[r0+8][kc*8+t+4]);
            }
            #pragma unroll
            for (int nt = 0; nt < 4; nt++) {
                int nc = wn + nt * 8 + g;
                unsigned bh0 = __float_as_uint(Bh[kc*8+t][nc]);
                unsigned bh1 = __float_as_uint(Bh[kc*8+t+4][nc]);
                unsigned bl0 = __float_as_uint(Bl[kc*8+t][nc]);
                unsigned bl1 = __float_as_uint(Bl[kc*8+t+4][nc]);
                #pragma unroll
                for (int mf = 0; mf < 2; mf++) {
                    MMA_TF32(acc[mf][nt], ah[mf][0], ah[mf][1], ah[mf][2], ah[mf][3], bh0, bh1);
                    MMA_TF32(acc[mf][nt], ah[mf][0], ah[mf][1], ah[mf][2], ah[mf][3], bl0, bl1);
                    MMA_TF32(acc[mf][nt], al[mf][0], al[mf][1], al[mf][2], al[mf][3], bh0, bh1);
                }
            }
        }
    }

    #pragma unroll
    for (int mf = 0; mf < 2; mf++) {
        #pragma unroll
        for (int rr = 0; rr < 2; rr++) {
            int m = m0 + wm + mf * 16 + g + rr * 8;
            #pragma unroll
            for (int nt = 0; nt < 4; nt++) {
                #pragma unroll
                for (int cc = 0; cc < 2; cc++) {
                    int j = n0 + wn + nt * 8 + 2 * t + cc;
                    float val = acc[mf][nt][rr * 2 + cc] + bias[j];
                    if (QKV) {
                        int b = m >> 11, l = m & 2047;
                        int ty = j >> 9, h = (j >> 6) & 7, d = j & 63;
                        float* dst = (ty == 0) ? g_q : (ty == 1) ? g_k : g_v;
                        dst[(((b * HH + h) * LL) + l) * DD + d] = val;
                    } else {
                        out[m * N + j] = val;
                    }
                }
            }
        }
    }
}

// ---------------- block means + min-cosine ----------------
template<int BLK, bool ISQ>
__global__ void __launch_bounds__(128) block_meta(int nb) {
    __shared__ float tile[BLK * 65];
    __shared__ float mean[64];
    __shared__ float red[128];
    __shared__ float nm_s;
    const float* t = ISQ ? g_q : g_k;
    float* mout = ISQ ? g_qm : g_km;
    float* simout = ISQ ? g_qsim : g_ksim;
    int blkid = blockIdx.x % nb;
    int bh = blockIdx.x / nb;
    const float* base = t + (bh * LL + blkid * BLK) * DD;
    int tid = threadIdx.x;
    for (int i = tid; i < BLK * DD; i += 128) {
        int r = i >> 6, d = i & 63;
        tile[r * 65 + d] = base[i];
    }
    __syncthreads();
    if (tid < 64) {
        float s = 0.f;
        for (int r = 0; r < BLK; r++) s += tile[r * 65 + tid];
        s *= (1.0f / BLK);
        mean[tid] = s;
        mout[blockIdx.x * 64 + tid] = s;
    }
    __syncthreads();
    if (tid == 0) {
        float s = 0.f;
        for (int d = 0; d < 64; d++) s += mean[d] * mean[d];
        nm_s = sqrtf(s) + 1e-6f;
    }
    __syncthreads();
    float mycos = CUDART_INF_F;
    if (tid < BLK) {
        float dot = 0.f, nr = 0.f;
        for (int d = 0; d < 64; d++) {
            float xv = tile[tid * 65 + d];
            dot += xv * mean[d];
            nr += xv * xv;
        }
        mycos = dot / ((sqrtf(nr) + 1e-6f) * nm_s);
    }
    red[tid] = mycos;
    __syncthreads();
    for (int s = 64; s > 0; s >>= 1) {
        if (tid < s) red[tid] = fminf(red[tid], red[tid + s]);
        __syncthreads();
    }
    if (tid == 0) simout[blockIdx.x] = red[0];
}

// ---------------- pooled softmax + CDF keep mask -> compacted kept-block lists ----------------
__global__ void __launch_bounds__(512) mask_kernel() {
    __shared__ float qm_s[NQ * DD];
    __shared__ float km_s[NK * DD];
    __shared__ float pooled[NQ][NK + 1];
    __shared__ float ksim_s[NK];
    int bh = blockIdx.x;
    int tid = threadIdx.x;
    for (int i = tid; i < NQ * DD; i += 512) qm_s[i] = g_qm[bh * NQ * DD + i];
    for (int i = tid; i < NK * DD; i += 512) km_s[i] = g_km[bh * NK * DD + i];
    if (tid < NK) ksim_s[tid] = g_ksim[bh * NK + tid];
    __syncthreads();
    {
        int qi = tid >> 5, j = tid & 31;
        const float* qv = &qm_s[qi * DD];
        const float* kv = &km_s[j * DD];
        float dot = 0.f;
        #pragma unroll
        for (int d = 0; d < DD; d++) dot += qv[d] * kv[d];
        pooled[qi][j] = dot * 0.125f;
    }
    __syncthreads();
    int w = tid >> 5;
    int lane = tid & 31;
    float v = pooled[w][lane];
    float mx = v;
    #pragma unroll
    for (int s = 16; s > 0; s >>= 1) mx = fmaxf(mx, __shfl_xor_sync(0xffffffffu, mx, s));
    float p = expf(v - mx);
    float sum = p;
    #pragma unroll
    for (int s = 16; s > 0; s >>= 1) sum += __shfl_xor_sync(0xffffffffu, sum, s);
    p /= sum;
    float sv = p;
    int si = lane;
    #pragma unroll
    for (int k = 2; k <= 32; k <<= 1) {
        #pragma unroll
        for (int j = k >> 1; j > 0; j >>= 1) {
            float ov = __shfl_xor_sync(0xffffffffu, sv, j);
            int   oi = __shfl_xor_sync(0xffffffffu, si, j);
            bool iprecede = (sv > ov) || (sv == ov && si < oi);
            bool lower = ((lane & j) == 0);
            bool dir = ((lane & k) == 0);
            bool keep_mine = ((lower == iprecede) == dir);
            if (!keep_mine) { sv = ov; si = oi; }
        }
    }
    float csum = sv;
    #pragma unroll
    for (int s = 1; s < 32; s <<= 1) {
        float t = __shfl_up_sync(0xffffffffu, csum, s);
        if (lane >= s) csum += t;
    }
    bool kept_sorted = (csum - sv) < 0.98f;
    unsigned keepmask = __reduce_or_sync(0xffffffffu, kept_sorted ? (1u << si) : 0u);
    bool qself = g_qsim[bh * NQ + w] > 0.6f;
    bool kself = ksim_s[lane] > 0.6f;
    bool fin = ((keepmask >> lane) & 1u) || !qself || !kself;
    unsigned fmask = __ballot_sync(0xffffffffu, fin);
    int pos = __popc(fmask & ((1u << lane) - 1u));
    int rowid = bh * NQ + w;
    if (fin) g_list[rowid * NK + pos] = lane;
    if (lane == 0) g_cnt[rowid] = __popc(fmask);
}

// ---------------- tf32 tensor-core flash attention ----------------
// CTA = full 128-row Q block of one (b,h); 256 threads, 8 warps x 16 rows.
// K/V staged once per (qb,kb), RNA-rounded to tf32 (truncation in the mma unit
// is biased -- explicit cvt.rna is required to stay at ~3e-4 rel err).
#define LDP 72
__global__ void __launch_bounds__(256) attn_kernel() {
    extern __shared__ float sm[];
    float* Ks = sm;                 // [64][LDP]
    float* Vs = sm + 64 * LDP;      // [64][LDP]
    float* Ps = sm + 128 * LDP;     // [128][LDP]

    int bh = blockIdx.y;
    int qb = blockIdx.x;
    int tid = threadIdx.x;
    int w = tid >> 5;
    int lane = tid & 31;
    int g = lane >> 2;
    int t = lane & 3;

    unsigned qa[8][4];
    {
        const float* q0 = g_q + (bh * LL + qb * 128 + w * 16 + g) * DD;
        const float* q1 = q0 + 8 * DD;
        #pragma unroll
        for (int kc = 0; kc < 8; kc++) {
            qa[kc][0] = f2tf(q0[kc * 8 + t] * 0.125f);
            qa[kc][1] = f2tf(q1[kc * 8 + t] * 0.125f);
            qa[kc][2] = f2tf(q0[kc * 8 + t + 4] * 0.125f);
            qa[kc][3] = f2tf(q1[kc * 8 + t + 4] * 0.125f);
        }
    }

    float oacc[8][4];
    #pragma unroll
    for (int dt = 0; dt < 8; dt++) { oacc[dt][0]=0.f; oacc[dt][1]=0.f; oacc[dt][2]=0.f; oacc[dt][3]=0.f; }
    float m0 = -CUDART_INF_F, m1 = -CUDART_INF_F;
    float l0 = 0.f, l1 = 0.f;

    int cnt = g_cnt[bh * NQ + qb];
    const int* __restrict__ list = g_list + (bh * NQ + qb) * NK;

    for (int it = 0; it < cnt; it++) {
        int kb = list[it];
        __syncthreads();
        {
            const float4* Kg = (const float4*)(g_k + (bh * LL + kb * BLKK) * DD);
            const float4* Vg = (const float4*)(g_v + (bh * LL + kb * BLKK) * DD);
            #pragma unroll
            for (int i = 0; i < 4; i++) {
                int idx = tid + i * 256;
                int row = idx >> 4, c4 = idx & 15;
                float4 kv = Kg[idx];
                float4 vv = Vg[idx];
                float* kd = &Ks[row * LDP + c4 * 4];
                kd[0] = f2tff(kv.x); kd[1] = f2tff(kv.y); kd[2] = f2tff(kv.z); kd[3] = f2tff(kv.w);
                float* vd = &Vs[row * LDP + c4 * 4];
                vd[0] = f2tff(vv.x); vd[1] = f2tff(vv.y); vd[2] = f2tff(vv.z); vd[3] = f2tff(vv.w);
            }
        }
        __syncthreads();

        float sc[8][4];
        #pragma unroll
        for (int nt = 0; nt < 8; nt++) { sc[nt][0]=0.f; sc[nt][1]=0.f; sc[nt][2]=0.f; sc[nt][3]=0.f; }
        #pragma unroll
        for (int kc = 0; kc < 8; kc++) {
            #pragma unroll
            for (int nt = 0; nt < 8; nt++) {
                unsigned b0 = __float_as_uint(Ks[(nt * 8 + g) * LDP + kc * 8 + t]);
                unsigned b1 = __float_as_uint(Ks[(nt * 8 + g) * LDP + kc * 8 + t + 4]);
                MMA_TF32(sc[nt], qa[kc][0], qa[kc][1], qa[kc][2], qa[kc][3], b0, b1);
            }
        }

        float mx0 = -CUDART_INF_F, mx1 = -CUDART_INF_F;
        #pragma unroll
        for (int nt = 0; nt < 8; nt++) {
            mx0 = fmaxf(mx0, fmaxf(sc[nt][0], sc[nt][1]));
            mx1 = fmaxf(mx1, fmaxf(sc[nt][2], sc[nt][3]));
        }
        mx0 = fmaxf(mx0, __shfl_xor_sync(0xffffffffu, mx0, 1));
        mx0 = fmaxf(mx0, __shfl_xor_sync(0xffffffffu, mx0, 2));
        mx1 = fmaxf(mx1, __shfl_xor_sync(0xffffffffu, mx1, 1));
        mx1 = fmaxf(mx1, __shfl_xor_sync(0xffffffffu, mx1, 2));
        float nm0 = fmaxf(m0, mx0);
        float nm1 = fmaxf(m1, mx1);
        float f0 = __expf(m0 - nm0);
        float f1 = __expf(m1 - nm1);
        #pragma unroll
        for (int dt = 0; dt < 8; dt++) {
            oacc[dt][0] *= f0; oacc[dt][1] *= f0;
            oacc[dt][2] *= f1; oacc[dt][3] *= f1;
        }
        l0 *= f0; l1 *= f1;
        m0 = nm0; m1 = nm1;

        float s0 = 0.f, s1 = 0.f;
        float* p0 = &Ps[(w * 16 + g) * LDP];
        float* p1 = &Ps[(w * 16 + g + 8) * LDP];
        #pragma unroll
        for (int nt = 0; nt < 8; nt++) {
            float e00 = __expf(sc[nt][0] - nm0);
            float e01 = __expf(sc[nt][1] - nm0);
            float e10 = __expf(sc[nt][2] - nm1);
            float e11 = __expf(sc[nt][3] - nm1);
            s0 += e00 + e01; s1 += e10 + e11;
            *(float2*)&p0[nt * 8 + 2 * t] = make_float2(f2tff(e00), f2tff(e01));
            *(float2*)&p1[nt * 8 + 2 * t] = make_float2(f2tff(e10), f2tff(e11));
        }
        s0 += __shfl_xor_sync(0xffffffffu, s0, 1);
        s0 += __shfl_xor_sync(0xffffffffu, s0, 2);
        s1 += __shfl_xor_sync(0xffffffffu, s1, 1);
        s1 += __shfl_xor_sync(0xffffffffu, s1, 2);
        l0 += s0; l1 += s1;
        __syncwarp();

        #pragma unroll
        for (int kc = 0; kc < 8; kc++) {
            unsigned a0 = __float_as_uint(Ps[(w * 16 + g) * LDP + kc * 8 + t]);
            unsigned a1 = __float_as_uint(Ps[(w * 16 + g + 8) * LDP + kc * 8 + t]);
            unsigned a2 = __float_as_uint(Ps[(w * 16 + g) * LDP + kc * 8 + t + 4]);
            unsigned a3 = __float_as_uint(Ps[(w * 16 + g + 8) * LDP + kc * 8 + t + 4]);
            #pragma unroll
            for (int dt = 0; dt < 8; dt++) {
                unsigned b0 = __float_as_uint(Vs[(kc * 8 + t) * LDP + dt * 8 + g]);
                unsigned b1 = __float_as_uint(Vs[(kc * 8 + t + 4) * LDP + dt * 8 + g]);
                MMA_TF32(oacc[dt], a0, a1, a2, a3, b0, b1);
            }
        }
        __syncwarp();
    }

    float inv0 = 1.0f / l0;
    float inv1 = 1.0f / l1;
    int b = bh >> 3, h = bh & 7;
    int grow = qb * 128 + w * 16 + g;
    float* o0 = g_ot + (b * LL + grow) * CC + h * DD;
    float* o1 = o0 + 8 * CC;
    #pragma unroll
    for (int dt = 0; dt < 8; dt++) {
        *(float2*)&o0[dt * 8 + 2 * t] = make_float2(oacc[dt][0] * inv0, oacc[dt][1] * inv0);
        *(float2*)&o1[dt * 8 + 2 * t] = make_float2(oacc[dt][2] * inv1, oacc[dt][3] * inv1);
    }
}

extern "C" void kernel_launch(void* const* d_in, const int* in_sizes, int n_in,
                              void* d_out, int out_size) {
    const float* x     = (const float*)d_in[0];
    const float* Wqkv  = (const float*)d_in[1];
    const float* bqkv  = (const float*)d_in[2];
    const float* Wproj = (const float*)d_in[3];
    const float* bproj = (const float*)d_in[4];
    float* out = (float*)d_out;

    dim3 g1(24, 64);                       // N=1536/64, M=4096/64
    gemm_tf32<3 * CC, true><<<g1, 128>>>(x, Wqkv, bqkv, nullptr);

    block_meta<BLKQ, true><<<BB * HH * NQ, 128>>>(NQ);
    block_meta<BLKK, false><<<BB * HH * NK, 128>>>(NK);

    mask_kernel<<<BB * HH, 512>>>();

    const int smem = 256 * LDP * sizeof(float);   // 73728 B
    cudaFuncSetAttribute(attn_kernel, cudaFuncAttributeMaxDynamicSharedMemorySize, smem);
    dim3 ga(NQ, BB * HH);
    attn_kernel<<<ga, 256, smem>>>();

    dim3 g2(8, 64);                        // N=512/64, M=4096/64
    gemm_tf32<CC, false><<<g2, 128>>>(nullptr, Wproj, bproj, out);
}

// round 11
// speedup vs baseline: 1.2309x; 1.2309x over previous
#include <cuda_runtime.h>
#include <cuda_fp16.h>
#include <math_constants.h>

#define BB 2
#define HH 8
#define LL 2048
#define DD 64
#define CC 512
#define NQ 16
#define NK 32
#define BLKQ 128
#define BLKK 64

// ---------------- scratch (no allocations allowed) ----------------
__device__ float g_q[BB*HH*LL*DD];
__device__ float g_k[BB*HH*LL*DD];
__device__ float g_v[BB*HH*LL*DD];
__device__ float g_qm[BB*HH*NQ*DD];
__device__ float g_km[BB*HH*NK*DD];
__device__ float g_qsim[BB*HH*NQ];
__device__ float g_ksim[BB*HH*NK];
__device__ int   g_cnt[BB*HH*NQ];
__device__ int   g_list[BB*HH*NQ*NK];
__device__ float g_ot[BB*LL*CC];

__device__ __forceinline__ unsigned f2tf(float x) {
    unsigned r;
    asm("cvt.rna.tf32.f32 %0, %1;" : "=r"(r) : "f"(x));
    return r;
}
__device__ __forceinline__ float f2tff(float x) { return __uint_as_float(f2tf(x)); }

__device__ __forceinline__ unsigned pkh2(float a, float b) {
    __half2 h = __floats2half2_rn(a, b);
    return *(unsigned*)&h;
}

#define MMA_TF32(c, a0, a1, a2, a3, b0, b1)                                   \
    asm volatile(                                                             \
        "mma.sync.aligned.m16n8k8.row.col.f32.tf32.tf32.f32 "                 \
        "{%0,%1,%2,%3},{%4,%5,%6,%7},{%8,%9},{%0,%1,%2,%3};"                  \
        : "+f"((c)[0]), "+f"((c)[1]), "+f"((c)[2]), "+f"((c)[3])              \
        : "r"(a0), "r"(a1), "r"(a2), "r"(a3), "r"(b0), "r"(b1))

#define MMA_F16(c, a0, a1, a2, a3, b0, b1)                                    \
    asm volatile(                                                             \
        "mma.sync.aligned.m16n8k16.row.col.f32.f16.f16.f32 "                  \
        "{%0,%1,%2,%3},{%4,%5,%6,%7},{%8,%9},{%0,%1,%2,%3};"                  \
        : "+f"((c)[0]), "+f"((c)[1]), "+f"((c)[2]), "+f"((c)[3])              \
        : "r"(a0), "r"(a1), "r"(a2), "r"(a3), "r"(b0), "r"(b1))

// ---------------- 3xTF32 tensor-core GEMM with register prefetch ----------------
template<int N, bool QKV>
__global__ void __launch_bounds__(128) gemm_tf32(const float* __restrict__ Ain,
                                                 const float* __restrict__ W,
                                                 const float* __restrict__ bias,
                                                 float* __restrict__ out) {
    __shared__ float Ah[64][36], Al[64][36];
    __shared__ float Bh[32][72], Bl[32][72];
    const float* __restrict__ A = QKV ? Ain : (const float*)g_ot;
    const int K = CC;
    int tid = threadIdx.x;
    int w = tid >> 5, lane = tid & 31;
    int g = lane >> 2, t = lane & 3;
    int wm = (w & 1) * 32, wn = (w >> 1) * 32;
    int m0 = blockIdx.y * 64, n0 = blockIdx.x * 64;

    int arow = tid >> 3, ac4 = (tid & 7) * 4;
    int brow = tid >> 4, bc4 = (tid & 15) * 4;

    float4 pa[4], pb[4];
    #pragma unroll
    for (int i = 0; i < 4; i++) {
        pa[i] = *(const float4*)&A[(m0 + arow + i * 16) * K + ac4];
        pb[i] = *(const float4*)&W[(brow + i * 8) * N + n0 + bc4];
    }

    float acc[2][4][4] = {};

    for (int k0 = 0; k0 < K; k0 += 32) {
        __syncthreads();
        #pragma unroll
        for (int i = 0; i < 4; i++) {
            float4 v = pa[i];
            int row = arow + i * 16;
            float h0 = f2tff(v.x), h1 = f2tff(v.y), h2 = f2tff(v.z), h3 = f2tff(v.w);
            Ah[row][ac4+0] = h0; Ah[row][ac4+1] = h1; Ah[row][ac4+2] = h2; Ah[row][ac4+3] = h3;
            Al[row][ac4+0] = f2tff(v.x - h0); Al[row][ac4+1] = f2tff(v.y - h1);
            Al[row][ac4+2] = f2tff(v.z - h2); Al[row][ac4+3] = f2tff(v.w - h3);
            v = pb[i];
            row = brow + i * 8;
            h0 = f2tff(v.x); h1 = f2tff(v.y); h2 = f2tff(v.z); h3 = f2tff(v.w);
            Bh[row][bc4+0] = h0; Bh[row][bc4+1] = h1; Bh[row][bc4+2] = h2; Bh[row][bc4+3] = h3;
            Bl[row][bc4+0] = f2tff(v.x - h0); Bl[row][bc4+1] = f2tff(v.y - h1);
            Bl[row][bc4+2] = f2tff(v.z - h2); Bl[row][bc4+3] = f2tff(v.w - h3);
        }
        __syncthreads();
        if (k0 + 32 < K) {
            #pragma unroll
            for (int i = 0; i < 4; i++) {
                pa[i] = *(const float4*)&A[(m0 + arow + i * 16) * K + k0 + 32 + ac4];
                pb[i] = *(const float4*)&W[(k0 + 32 + brow + i * 8) * N + n0 + bc4];
            }
        }
        #pragma unroll
        for (int kc = 0; kc < 4; kc++) {
            unsigned ah[2][4], al[2][4];
            #pragma unroll
            for (int mf = 0; mf < 2; mf++) {
                int r0 = wm + mf * 16 + g;
                ah[mf][0] = __float_as_uint(Ah[r0][kc*8+t]);
                ah[mf][1] = __float_as_uint(Ah[r0+8][kc*8+t]);
                ah[mf][2] = __float_as_uint(Ah[r0][kc*8+t+4]);
                ah[mf][3] = __float_as_uint(Ah[r0+8][kc*8+t+4]);
                al[mf][0] = __float_as_uint(Al[r0][kc*8+t]);
                al[mf][1] = __float_as_uint(Al[r0+8][kc*8+t]);
                al[mf][2] = __float_as_uint(Al[r0][kc*8+t+4]);
                al[mf][3] = __float_as_uint(Al[r0+8][kc*8+t+4]);
            }
            #pragma unroll
            for (int nt = 0; nt < 4; nt++) {
                int nc = wn + nt * 8 + g;
                unsigned bh0 = __float_as_uint(Bh[kc*8+t][nc]);
                unsigned bh1 = __float_as_uint(Bh[kc*8+t+4][nc]);
                unsigned bl0 = __float_as_uint(Bl[kc*8+t][nc]);
                unsigned bl1 = __float_as_uint(Bl[kc*8+t+4][nc]);
                #pragma unroll
                for (int mf = 0; mf < 2; mf++) {
                    MMA_TF32(acc[mf][nt], ah[mf][0], ah[mf][1], ah[mf][2], ah[mf][3], bh0, bh1);
                    MMA_TF32(acc[mf][nt], ah[mf][0], ah[mf][1], ah[mf][2], ah[mf][3], bl0, bl1);
                    MMA_TF32(acc[mf][nt], al[mf][0], al[mf][1], al[mf][2], al[mf][3], bh0, bh1);
                }
            }
        }
    }

    #pragma unroll
    for (int mf = 0; mf < 2; mf++) {
        #pragma unroll
        for (int rr = 0; rr < 2; rr++) {
            int m = m0 + wm + mf * 16 + g + rr * 8;
            #pragma unroll
            for (int nt = 0; nt < 4; nt++) {
                #pragma unroll
                for (int cc = 0; cc < 2; cc++) {
                    int j = n0 + wn + nt * 8 + 2 * t + cc;
                    float val = acc[mf][nt][rr * 2 + cc] + bias[j];
                    if (QKV) {
                        int b = m >> 11, l = m & 2047;
                        int ty = j >> 9, h = (j >> 6) & 7, d = j & 63;
                        float* dst = (ty == 0) ? g_q : (ty == 1) ? g_k : g_v;
                        dst[(((b * HH + h) * LL) + l) * DD + d] = val;
                    } else {
                        out[m * N + j] = val;
                    }
                }
            }
        }
    }
}

// ---------------- block means + min-cosine ----------------
template<int BLK, bool ISQ>
__global__ void __launch_bounds__(128) block_meta(int nb) {
    __shared__ float tile[BLK * 65];
    __shared__ float mean[64];
    __shared__ float red[128];
    __shared__ float nm_s;
    const float* t = ISQ ? g_q : g_k;
    float* mout = ISQ ? g_qm : g_km;
    float* simout = ISQ ? g_qsim : g_ksim;
    int blkid = blockIdx.x % nb;
    int bh = blockIdx.x / nb;
    const float* base = t + (bh * LL + blkid * BLK) * DD;
    int tid = threadIdx.x;
    for (int i = tid; i < BLK * DD; i += 128) {
        int r = i >> 6, d = i & 63;
        tile[r * 65 + d] = base[i];
    }
    __syncthreads();
    if (tid < 64) {
        float s = 0.f;
        for (int r = 0; r < BLK; r++) s += tile[r * 65 + tid];
        s *= (1.0f / BLK);
        mean[tid] = s;
        mout[blockIdx.x * 64 + tid] = s;
    }
    __syncthreads();
    if (tid == 0) {
        float s = 0.f;
        for (int d = 0; d < 64; d++) s += mean[d] * mean[d];
        nm_s = sqrtf(s) + 1e-6f;
    }
    __syncthreads();
    float mycos = CUDART_INF_F;
    if (tid < BLK) {
        float dot = 0.f, nr = 0.f;
        for (int d = 0; d < 64; d++) {
            float xv = tile[tid * 65 + d];
            dot += xv * mean[d];
            nr += xv * xv;
        }
        mycos = dot / ((sqrtf(nr) + 1e-6f) * nm_s);
    }
    red[tid] = mycos;
    __syncthreads();
    for (int s = 64; s > 0; s >>= 1) {
        if (tid < s) red[tid] = fminf(red[tid], red[tid + s]);
        __syncthreads();
    }
    if (tid == 0) simout[blockIdx.x] = red[0];
}

// ---------------- pooled softmax + CDF keep mask -> compacted kept-block lists ----------------
__global__ void __launch_bounds__(512) mask_kernel() {
    __shared__ float qm_s[NQ * DD];
    __shared__ float km_s[NK * DD];
    __shared__ float pooled[NQ][NK + 1];
    __shared__ float ksim_s[NK];
    int bh = blockIdx.x;
    int tid = threadIdx.x;
    for (int i = tid; i < NQ * DD; i += 512) qm_s[i] = g_qm[bh * NQ * DD + i];
    for (int i = tid; i < NK * DD; i += 512) km_s[i] = g_km[bh * NK * DD + i];
    if (tid < NK) ksim_s[tid] = g_ksim[bh * NK + tid];
    __syncthreads();
    {
        int qi = tid >> 5, j = tid & 31;
        const float* qv = &qm_s[qi * DD];
        const float* kv = &km_s[j * DD];
        float dot = 0.f;
        #pragma unroll
        for (int d = 0; d < DD; d++) dot += qv[d] * kv[d];
        pooled[qi][j] = dot * 0.125f;
    }
    __syncthreads();
    int w = tid >> 5;
    int lane = tid & 31;
    float v = pooled[w][lane];
    float mx = v;
    #pragma unroll
    for (int s = 16; s > 0; s >>= 1) mx = fmaxf(mx, __shfl_xor_sync(0xffffffffu, mx, s));
    float p = expf(v - mx);
    float sum = p;
    #pragma unroll
    for (int s = 16; s > 0; s >>= 1) sum += __shfl_xor_sync(0xffffffffu, sum, s);
    p /= sum;
    float sv = p;
    int si = lane;
    #pragma unroll
    for (int k = 2; k <= 32; k <<= 1) {
        #pragma unroll
        for (int j = k >> 1; j > 0; j >>= 1) {
            float ov = __shfl_xor_sync(0xffffffffu, sv, j);
            int   oi = __shfl_xor_sync(0xffffffffu, si, j);
            bool iprecede = (sv > ov) || (sv == ov && si < oi);
            bool lower = ((lane & j) == 0);
            bool dir = ((lane & k) == 0);
            bool keep_mine = ((lower == iprecede) == dir);
            if (!keep_mine) { sv = ov; si = oi; }
        }
    }
    float csum = sv;
    #pragma unroll
    for (int s = 1; s < 32; s <<= 1) {
        float t = __shfl_up_sync(0xffffffffu, csum, s);
        if (lane >= s) csum += t;
    }
    bool kept_sorted = (csum - sv) < 0.98f;
    unsigned keepmask = __reduce_or_sync(0xffffffffu, kept_sorted ? (1u << si) : 0u);
    bool qself = g_qsim[bh * NQ + w] > 0.6f;
    bool kself = ksim_s[lane] > 0.6f;
    bool fin = ((keepmask >> lane) & 1u) || !qself || !kself;
    unsigned fmask = __ballot_sync(0xffffffffu, fin);
    int pos = __popc(fmask & ((1u << lane) - 1u));
    int rowid = bh * NQ + w;
    if (fin) g_list[rowid * NK + pos] = lane;
    if (lane == 0) g_cnt[rowid] = __popc(fmask);
}

// ---------------- fp16 tensor-core flash attention (m16n8k16) ----------------
// CTA = 128 Q rows, 256 threads, 8 warps x 16 rows. K/V/P in fp16 (RN-rounded;
// same 10-bit mantissa as tf32), fp32 accumulators. V staged transposed so PV
// B-fragments are contiguous half2. LDH=72-half row padding -> fragment loads
// hit bank (4g+t+8kc): conflict-free. Next block's K/V prefetched to registers.
#define LDH 72
__global__ void __launch_bounds__(256) attn_kernel() {
    extern __shared__ __half smh[];
    __half* Ks = smh;               // [64 keys][LDH]  (key-major, d contiguous)
    __half* Vt = smh + 64 * LDH;    // [64 d][LDH]     (d-major, key contiguous)
    __half* Ps = smh + 128 * LDH;   // [128 q][LDH]

    int bh = blockIdx.y;
    int qb = blockIdx.x;
    int tid = threadIdx.x;
    int w = tid >> 5;
    int lane = tid & 31;
    int g = lane >> 2;
    int t = lane & 3;

    // Q fragments (rows w*16+g, +8), pre-scaled, fp16 RN
    unsigned qa[4][4];
    {
        const float* q0 = g_q + (bh * LL + qb * 128 + w * 16 + g) * DD;
        const float* q1 = q0 + 8 * DD;
        #pragma unroll
        for (int kc = 0; kc < 4; kc++) {
            int c = kc * 16 + 2 * t;
            qa[kc][0] = pkh2(q0[c] * 0.125f,     q0[c + 1] * 0.125f);
            qa[kc][1] = pkh2(q1[c] * 0.125f,     q1[c + 1] * 0.125f);
            qa[kc][2] = pkh2(q0[c + 8] * 0.125f, q0[c + 9] * 0.125f);
            qa[kc][3] = pkh2(q1[c + 8] * 0.125f, q1[c + 9] * 0.125f);
        }
    }

    float oacc[8][4];
    #pragma unroll
    for (int dt = 0; dt < 8; dt++) { oacc[dt][0]=0.f; oacc[dt][1]=0.f; oacc[dt][2]=0.f; oacc[dt][3]=0.f; }
    float m0 = -CUDART_INF_F, m1 = -CUDART_INF_F;
    float l0 = 0.f, l1 = 0.f;

    int cnt = g_cnt[bh * NQ + qb];
    const int* __restrict__ list = g_list + (bh * NQ + qb) * NK;

    int srow = tid >> 4, sc4 = (tid & 15) * 4;   // staging: key row, d quad
    float4 pk[4], pv[4];
    if (cnt > 0) {
        int kb = list[0];
        const float4* Kg = (const float4*)(g_k + (bh * LL + kb * BLKK) * DD);
        const float4* Vg = (const float4*)(g_v + (bh * LL + kb * BLKK) * DD);
        #pragma unroll
        for (int i = 0; i < 4; i++) { pk[i] = Kg[tid + i * 256]; pv[i] = Vg[tid + i * 256]; }
    }

    for (int it = 0; it < cnt; it++) {
        __syncthreads();
        // stage prefetched K/V into smem (fp16 RN; V transposed)
        #pragma unroll
        for (int i = 0; i < 4; i++) {
            int idx = tid + i * 256;
            int row = idx >> 4, c4 = (idx & 15) * 4;
            float4 kv = pk[i];
            *(__half2*)&Ks[row * LDH + c4]     = __floats2half2_rn(kv.x, kv.y);
            *(__half2*)&Ks[row * LDH + c4 + 2] = __floats2half2_rn(kv.z, kv.w);
            float4 vv = pv[i];
            Vt[(c4 + 0) * LDH + row] = __float2half_rn(vv.x);
            Vt[(c4 + 1) * LDH + row] = __float2half_rn(vv.y);
            Vt[(c4 + 2) * LDH + row] = __float2half_rn(vv.z);
            Vt[(c4 + 3) * LDH + row] = __float2half_rn(vv.w);
        }
        __syncthreads();
        if (it + 1 < cnt) {
            int kb = list[it + 1];
            const float4* Kg = (const float4*)(g_k + (bh * LL + kb * BLKK) * DD);
            const float4* Vg = (const float4*)(g_v + (bh * LL + kb * BLKK) * DD);
            #pragma unroll
            for (int i = 0; i < 4; i++) { pk[i] = Kg[tid + i * 256]; pv[i] = Vg[tid + i * 256]; }
        }

        // S = Q K^T  (16 x 64 per warp)
        float sc[8][4];
        #pragma unroll
        for (int nt = 0; nt < 8; nt++) { sc[nt][0]=0.f; sc[nt][1]=0.f; sc[nt][2]=0.f; sc[nt][3]=0.f; }
        #pragma unroll
        for (int kc = 0; kc < 4; kc++) {
            #pragma unroll
            for (int nt = 0; nt < 8; nt++) {
                unsigned b0 = *(const unsigned*)&Ks[(nt * 8 + g) * LDH + kc * 16 + 2 * t];
                unsigned b1 = *(const unsigned*)&Ks[(nt * 8 + g) * LDH + kc * 16 + 2 * t + 8];
                MMA_F16(sc[nt], qa[kc][0], qa[kc][1], qa[kc][2], qa[kc][3], b0, b1);
            }
        }

        // online softmax
        float mx0 = -CUDART_INF_F, mx1 = -CUDART_INF_F;
        #pragma unroll
        for (int nt = 0; nt < 8; nt++) {
            mx0 = fmaxf(mx0, fmaxf(sc[nt][0], sc[nt][1]));
            mx1 = fmaxf(mx1, fmaxf(sc[nt][2], sc[nt][3]));
        }
        mx0 = fmaxf(mx0, __shfl_xor_sync(0xffffffffu, mx0, 1));
        mx0 = fmaxf(mx0, __shfl_xor_sync(0xffffffffu, mx0, 2));
        mx1 = fmaxf(mx1, __shfl_xor_sync(0xffffffffu, mx1, 1));
        mx1 = fmaxf(mx1, __shfl_xor_sync(0xffffffffu, mx1, 2));
        float nm0 = fmaxf(m0, mx0);
        float nm1 = fmaxf(m1, mx1);
        float f0 = __expf(m0 - nm0);
        float f1 = __expf(m1 - nm1);
        #pragma unroll
        for (int dt = 0; dt < 8; dt++) {
            oacc[dt][0] *= f0; oacc[dt][1] *= f0;
            oacc[dt][2] *= f1; oacc[dt][3] *= f1;
        }
        l0 *= f0; l1 *= f1;
        m0 = nm0; m1 = nm1;

        float s0 = 0.f, s1 = 0.f;
        __half* p0 = &Ps[(w * 16 + g) * LDH];
        __half* p1 = &Ps[(w * 16 + g + 8) * LDH];
        #pragma unroll
        for (int nt = 0; nt < 8; nt++) {
            float e00 = __expf(sc[nt][0] - nm0);
            float e01 = __expf(sc[nt][1] - nm0);
            float e10 = __expf(sc[nt][2] - nm1);
            float e11 = __expf(sc[nt][3] - nm1);
            s0 += e00 + e01; s1 += e10 + e11;
            *(__half2*)&p0[nt * 8 + 2 * t] = __floats2half2_rn(e00, e01);
            *(__half2*)&p1[nt * 8 + 2 * t] = __floats2half2_rn(e10, e11);
        }
        s0 += __shfl_xor_sync(0xffffffffu, s0, 1);
        s0 += __shfl_xor_sync(0xffffffffu, s0, 2);
        s1 += __shfl_xor_sync(0xffffffffu, s1, 1);
        s1 += __shfl_xor_sync(0xffffffffu, s1, 2);
        l0 += s0; l1 += s1;
        __syncwarp();

        // O += P V   (each warp reads only its own P rows)
        #pragma unroll
        for (int kc = 0; kc < 4; kc++) {
            unsigned a0 = *(const unsigned*)&Ps[(w * 16 + g) * LDH + kc * 16 + 2 * t];
            unsigned a1 = *(const unsigned*)&Ps[(w * 16 + g + 8) * LDH + kc * 16 + 2 * t];
            unsigned a2 = *(const unsigned*)&Ps[(w * 16 + g) * LDH + kc * 16 + 2 * t + 8];
            unsigned a3 = *(const unsigned*)&Ps[(w * 16 + g + 8) * LDH + kc * 16 + 2 * t + 8];
            #pragma unroll
            for (int dt = 0; dt < 8; dt++) {
                unsigned b0 = *(const unsigned*)&Vt[(dt * 8 + g) * LDH + kc * 16 + 2 * t];
                unsigned b1 = *(const unsigned*)&Vt[(dt * 8 + g) * LDH + kc * 16 + 2 * t + 8];
                MMA_F16(oacc[dt], a0, a1, a2, a3, b0, b1);
            }
        }
        __syncwarp();
    }

    float inv0 = 1.0f / l0;
    float inv1 = 1.0f / l1;
    int b = bh >> 3, h = bh & 7;
    int grow = qb * 128 + w * 16 + g;
    float* o0 = g_ot + (b * LL + grow) * CC + h * DD;
    float* o1 = o0 + 8 * CC;
    #pragma unroll
    for (int dt = 0; dt < 8; dt++) {
        *(float2*)&o0[dt * 8 + 2 * t] = make_float2(oacc[dt][0] * inv0, oacc[dt][1] * inv0);
        *(float2*)&o1[dt * 8 + 2 * t] = make_float2(oacc[dt][2] * inv1, oacc[dt][3] * inv1);
    }
}

extern "C" void kernel_launch(void* const* d_in, const int* in_sizes, int n_in,
                              void* d_out, int out_size) {
    const float* x     = (const float*)d_in[0];
    const float* Wqkv  = (const float*)d_in[1];
    const float* bqkv  = (const float*)d_in[2];
    const float* Wproj = (const float*)d_in[3];
    const float* bproj = (const float*)d_in[4];
    float* out = (float*)d_out;

    dim3 g1(24, 64);                       // N=1536/64, M=4096/64
    gemm_tf32<3 * CC, true><<<g1, 128>>>(x, Wqkv, bqkv, nullptr);

    block_meta<BLKQ, true><<<BB * HH * NQ, 128>>>(NQ);
    block_meta<BLKK, false><<<BB * HH * NK, 128>>>(NK);

    mask_kernel<<<BB * HH, 512>>>();

    const int smem = 256 * LDH * sizeof(__half);   // 36864 B
    cudaFuncSetAttribute(attn_kernel, cudaFuncAttributeMaxDynamicSharedMemorySize, smem);
    dim3 ga(NQ, BB * HH);
    attn_kernel<<<ga, 256, smem>>>();

    dim3 g2(8, 64);                        // N=512/64, M=4096/64
    gemm_tf32<CC, false><<<g2, 128>>>(nullptr, Wproj, bproj, out);
}

// round 12
// speedup vs baseline: 1.3091x; 1.0635x over previous
#include <cuda_runtime.h>
#include <cuda_fp16.h>
#include <math_constants.h>

#define BB 2
#define HH 8
#define LL 2048
#define DD 64
#define CC 512
#define NQ 16
#define NK 32
#define BLKQ 128
#define BLKK 64

// ---------------- scratch (no allocations allowed) ----------------
__device__ float g_q[BB*HH*LL*DD];
__device__ float g_k[BB*HH*LL*DD];
__device__ float g_v[BB*HH*LL*DD];
__device__ float g_qm[BB*HH*NQ*DD];
__device__ float g_km[BB*HH*NK*DD];
__device__ float g_qsim[BB*HH*NQ];
__device__ float g_ksim[BB*HH*NK];
__device__ int   g_cnt[BB*HH*NQ];
__device__ int   g_list[BB*HH*NQ*NK];
__device__ float g_ot[BB*LL*CC];

__device__ __forceinline__ unsigned pkh2(float a, float b) {
    __half2 h = __floats2half2_rn(a, b);
    return *(unsigned*)&h;
}

#define MMA_F16(c, a0, a1, a2, a3, b0, b1)                                    \
    asm volatile(                                                             \
        "mma.sync.aligned.m16n8k16.row.col.f32.f16.f16.f32 "                  \
        "{%0,%1,%2,%3},{%4,%5,%6,%7},{%8,%9},{%0,%1,%2,%3};"                  \
        : "+f"((c)[0]), "+f"((c)[1]), "+f"((c)[2]), "+f"((c)[3])              \
        : "r"(a0), "r"(a1), "r"(a2), "r"(a3), "r"(b0), "r"(b1))

// ---------------- split-fp16 tensor-core GEMM (near-fp32 accuracy) ----------------
// CTA 64x64 tile, 128 threads (4 warps, 32x32 quadrants), k-chunk 32.
// 2-term split: a*b ~= ah*bh + ah*bl + al*bh, residual ~2^-20 relative.
// A staged [m][k] (k contiguous), B staged TRANSPOSED [n][k] so both A and B
// fragments are contiguous half2 loads (layouts validated by the attn kernel).
#define LDA 40
#define LDB 42
template<int N, bool QKV>
__global__ void __launch_bounds__(128) gemm_f16(const float* __restrict__ Ain,
                                                const float* __restrict__ W,
                                                const float* __restrict__ bias,
                                                float* __restrict__ out) {
    __shared__ __half Ahi[64][LDA], Alo[64][LDA];
    __shared__ __half Bhi[64][LDB], Blo[64][LDB];
    const float* __restrict__ A = QKV ? Ain : (const float*)g_ot;
    const int K = CC;
    int tid = threadIdx.x;
    int w = tid >> 5, lane = tid & 31;
    int g = lane >> 2, t = lane & 3;
    int wm = (w & 1) * 32, wn = (w >> 1) * 32;
    int m0 = blockIdx.y * 64, n0 = blockIdx.x * 64;

    int arow = tid >> 3, ac4 = (tid & 7) * 4;   // A tile 64x32 floats
    int brow = tid >> 4, bc4 = (tid & 15) * 4;  // W tile 32x64 floats

    float4 pa[4], pb[4];
    #pragma unroll
    for (int i = 0; i < 4; i++) {
        pa[i] = *(const float4*)&A[(m0 + arow + i * 16) * K + ac4];
        pb[i] = *(const float4*)&W[(brow + i * 8) * N + n0 + bc4];
    }

    float acc[2][4][4] = {};

    for (int k0 = 0; k0 < K; k0 += 32) {
        __syncthreads();
        #pragma unroll
        for (int i = 0; i < 4; i++) {
            // A: hi/lo split, [m][k]
            float4 v = pa[i];
            int row = arow + i * 16;
            __half h0 = __float2half_rn(v.x), h1 = __float2half_rn(v.y);
            __half h2 = __float2half_rn(v.z), h3 = __float2half_rn(v.w);
            Ahi[row][ac4+0] = h0; Ahi[row][ac4+1] = h1;
            Ahi[row][ac4+2] = h2; Ahi[row][ac4+3] = h3;
            Alo[row][ac4+0] = __float2half_rn(v.x - __half2float(h0));
            Alo[row][ac4+1] = __float2half_rn(v.y - __half2float(h1));
            Alo[row][ac4+2] = __float2half_rn(v.z - __half2float(h2));
            Alo[row][ac4+3] = __float2half_rn(v.w - __half2float(h3));
            // B: hi/lo split, transposed to [n][k]
            v = pb[i];
            int krow = brow + i * 8;
            h0 = __float2half_rn(v.x); h1 = __float2half_rn(v.y);
            h2 = __float2half_rn(v.z); h3 = __float2half_rn(v.w);
            Bhi[bc4+0][krow] = h0; Bhi[bc4+1][krow] = h1;
            Bhi[bc4+2][krow] = h2; Bhi[bc4+3][krow] = h3;
            Blo[bc4+0][krow] = __float2half_rn(v.x - __half2float(h0));
            Blo[bc4+1][krow] = __float2half_rn(v.y - __half2float(h1));
            Blo[bc4+2][krow] = __float2half_rn(v.z - __half2float(h2));
            Blo[bc4+3][krow] = __float2half_rn(v.w - __half2float(h3));
        }
        __syncthreads();
        if (k0 + 32 < K) {
            #pragma unroll
            for (int i = 0; i < 4; i++) {
                pa[i] = *(const float4*)&A[(m0 + arow + i * 16) * K + k0 + 32 + ac4];
                pb[i] = *(const float4*)&W[(k0 + 32 + brow + i * 8) * N + n0 + bc4];
            }
        }
        #pragma unroll
        for (int kc = 0; kc < 2; kc++) {
            int c = kc * 16 + 2 * t;
            unsigned ahi[2][4], alo[2][4];
            #pragma unroll
            for (int mf = 0; mf < 2; mf++) {
                int r0 = wm + mf * 16 + g;
                ahi[mf][0] = *(const unsigned*)&Ahi[r0][c];
                ahi[mf][1] = *(const unsigned*)&Ahi[r0+8][c];
                ahi[mf][2] = *(const unsigned*)&Ahi[r0][c+8];
                ahi[mf][3] = *(const unsigned*)&Ahi[r0+8][c+8];
                alo[mf][0] = *(const unsigned*)&Alo[r0][c];
                alo[mf][1] = *(const unsigned*)&Alo[r0+8][c];
                alo[mf][2] = *(const unsigned*)&Alo[r0][c+8];
                alo[mf][3] = *(const unsigned*)&Alo[r0+8][c+8];
            }
            #pragma unroll
            for (int nt = 0; nt < 4; nt++) {
                int nr = wn + nt * 8 + g;
                unsigned bh0 = *(const unsigned*)&Bhi[nr][c];
                unsigned bh1 = *(const unsigned*)&Bhi[nr][c+8];
                unsigned bl0 = *(const unsigned*)&Blo[nr][c];
                unsigned bl1 = *(const unsigned*)&Blo[nr][c+8];
                #pragma unroll
                for (int mf = 0; mf < 2; mf++) {
                    MMA_F16(acc[mf][nt], ahi[mf][0], ahi[mf][1], ahi[mf][2], ahi[mf][3], bh0, bh1);
                    MMA_F16(acc[mf][nt], ahi[mf][0], ahi[mf][1], ahi[mf][2], ahi[mf][3], bl0, bl1);
                    MMA_F16(acc[mf][nt], alo[mf][0], alo[mf][1], alo[mf][2], alo[mf][3], bh0, bh1);
                }
            }
        }
    }

    #pragma unroll
    for (int mf = 0; mf < 2; mf++) {
        #pragma unroll
        for (int rr = 0; rr < 2; rr++) {
            int m = m0 + wm + mf * 16 + g + rr * 8;
            #pragma unroll
            for (int nt = 0; nt < 4; nt++) {
                #pragma unroll
                for (int cc = 0; cc < 2; cc++) {
                    int j = n0 + wn + nt * 8 + 2 * t + cc;
                    float val = acc[mf][nt][rr * 2 + cc] + bias[j];
                    if (QKV) {
                        int b = m >> 11, l = m & 2047;
                        int ty = j >> 9, h = (j >> 6) & 7, d = j & 63;
                        float* dst = (ty == 0) ? g_q : (ty == 1) ? g_k : g_v;
                        dst[(((b * HH + h) * LL) + l) * DD + d] = val;
                    } else {
                        out[m * N + j] = val;
                    }
                }
            }
        }
    }
}

// ---------------- block means + min-cosine ----------------
template<int BLK, bool ISQ>
__global__ void __launch_bounds__(128) block_meta(int nb) {
    __shared__ float tile[BLK * 65];
    __shared__ float mean[64];
    __shared__ float red[128];
    __shared__ float nm_s;
    const float* t = ISQ ? g_q : g_k;
    float* mout = ISQ ? g_qm : g_km;
    float* simout = ISQ ? g_qsim : g_ksim;
    int blkid = blockIdx.x % nb;
    int bh = blockIdx.x / nb;
    const float* base = t + (bh * LL + blkid * BLK) * DD;
    int tid = threadIdx.x;
    for (int i = tid; i < BLK * DD; i += 128) {
        int r = i >> 6, d = i & 63;
        tile[r * 65 + d] = base[i];
    }
    __syncthreads();
    if (tid < 64) {
        float s = 0.f;
        for (int r = 0; r < BLK; r++) s += tile[r * 65 + tid];
        s *= (1.0f / BLK);
        mean[tid] = s;
        mout[blockIdx.x * 64 + tid] = s;
    }
    __syncthreads();
    if (tid == 0) {
        float s = 0.f;
        for (int d = 0; d < 64; d++) s += mean[d] * mean[d];
        nm_s = sqrtf(s) + 1e-6f;
    }
    __syncthreads();
    float mycos = CUDART_INF_F;
    if (tid < BLK) {
        float dot = 0.f, nr = 0.f;
        for (int d = 0; d < 64; d++) {
            float xv = tile[tid * 65 + d];
            dot += xv * mean[d];
            nr += xv * xv;
        }
        mycos = dot / ((sqrtf(nr) + 1e-6f) * nm_s);
    }
    red[tid] = mycos;
    __syncthreads();
    for (int s = 64; s > 0; s >>= 1) {
        if (tid < s) red[tid] = fminf(red[tid], red[tid + s]);
        __syncthreads();
    }
    if (tid == 0) simout[blockIdx.x] = red[0];
}

// ---------------- pooled softmax + CDF keep mask -> compacted kept-block lists ----------------
__global__ void __launch_bounds__(512) mask_kernel() {
    __shared__ float qm_s[NQ * DD];
    __shared__ float km_s[NK * DD];
    __shared__ float pooled[NQ][NK + 1];
    __shared__ float ksim_s[NK];
    int bh = blockIdx.x;
    int tid = threadIdx.x;
    for (int i = tid; i < NQ * DD; i += 512) qm_s[i] = g_qm[bh * NQ * DD + i];
    for (int i = tid; i < NK * DD; i += 512) km_s[i] = g_km[bh * NK * DD + i];
    if (tid < NK) ksim_s[tid] = g_ksim[bh * NK + tid];
    __syncthreads();
    {
        int qi = tid >> 5, j = tid & 31;
        const float* qv = &qm_s[qi * DD];
        const float* kv = &km_s[j * DD];
        float dot = 0.f;
        #pragma unroll
        for (int d = 0; d < DD; d++) dot += qv[d] * kv[d];
        pooled[qi][j] = dot * 0.125f;
    }
    __syncthreads();
    int w = tid >> 5;
    int lane = tid & 31;
    float v = pooled[w][lane];
    float mx = v;
    #pragma unroll
    for (int s = 16; s > 0; s >>= 1) mx = fmaxf(mx, __shfl_xor_sync(0xffffffffu, mx, s));
    float p = expf(v - mx);
    float sum = p;
    #pragma unroll
    for (int s = 16; s > 0; s >>= 1) sum += __shfl_xor_sync(0xffffffffu, sum, s);
    p /= sum;
    float sv = p;
    int si = lane;
    #pragma unroll
    for (int k = 2; k <= 32; k <<= 1) {
        #pragma unroll
        for (int j = k >> 1; j > 0; j >>= 1) {
            float ov = __shfl_xor_sync(0xffffffffu, sv, j);
            int   oi = __shfl_xor_sync(0xffffffffu, si, j);
            bool iprecede = (sv > ov) || (sv == ov && si < oi);
            bool lower = ((lane & j) == 0);
            bool dir = ((lane & k) == 0);
            bool keep_mine = ((lower == iprecede) == dir);
            if (!keep_mine) { sv = ov; si = oi; }
        }
    }
    float csum = sv;
    #pragma unroll
    for (int s = 1; s < 32; s <<= 1) {
        float t = __shfl_up_sync(0xffffffffu, csum, s);
        if (lane >= s) csum += t;
    }
    bool kept_sorted = (csum - sv) < 0.98f;
    unsigned keepmask = __reduce_or_sync(0xffffffffu, kept_sorted ? (1u << si) : 0u);
    bool qself = g_qsim[bh * NQ + w] > 0.6f;
    bool kself = ksim_s[lane] > 0.6f;
    bool fin = ((keepmask >> lane) & 1u) || !qself || !kself;
    unsigned fmask = __ballot_sync(0xffffffffu, fin);
    int pos = __popc(fmask & ((1u << lane) - 1u));
    int rowid = bh * NQ + w;
    if (fin) g_list[rowid * NK + pos] = lane;
    if (lane == 0) g_cnt[rowid] = __popc(fmask);
}

// ---------------- fp16 tensor-core flash attention (m16n8k16) ----------------
#define LDH 72
__global__ void __launch_bounds__(256) attn_kernel() {
    extern __shared__ __half smh[];
    __half* Ks = smh;               // [64 keys][LDH]
    __half* Vt = smh + 64 * LDH;    // [64 d][LDH]
    __half* Ps = smh + 128 * LDH;   // [128 q][LDH]

    int bh = blockIdx.y;
    int qb = blockIdx.x;
    int tid = threadIdx.x;
    int w = tid >> 5;
    int lane = tid & 31;
    int g = lane >> 2;
    int t = lane & 3;

    unsigned qa[4][4];
    {
        const float* q0 = g_q + (bh * LL + qb * 128 + w * 16 + g) * DD;
        const float* q1 = q0 + 8 * DD;
        #pragma unroll
        for (int kc = 0; kc < 4; kc++) {
            int c = kc * 16 + 2 * t;
            qa[kc][0] = pkh2(q0[c] * 0.125f,     q0[c + 1] * 0.125f);
            qa[kc][1] = pkh2(q1[c] * 0.125f,     q1[c + 1] * 0.125f);
            qa[kc][2] = pkh2(q0[c + 8] * 0.125f, q0[c + 9] * 0.125f);
            qa[kc][3] = pkh2(q1[c + 8] * 0.125f, q1[c + 9] * 0.125f);
        }
    }

    float oacc[8][4];
    #pragma unroll
    for (int dt = 0; dt < 8; dt++) { oacc[dt][0]=0.f; oacc[dt][1]=0.f; oacc[dt][2]=0.f; oacc[dt][3]=0.f; }
    float m0 = -CUDART_INF_F, m1 = -CUDART_INF_F;
    float l0 = 0.f, l1 = 0.f;

    int cnt = g_cnt[bh * NQ + qb];
    const int* __restrict__ list = g_list + (bh * NQ + qb) * NK;

    float4 pk[4], pv[4];
    if (cnt > 0) {
        int kb = list[0];
        const float4* Kg = (const float4*)(g_k + (bh * LL + kb * BLKK) * DD);
        const float4* Vg = (const float4*)(g_v + (bh * LL + kb * BLKK) * DD);
        #pragma unroll
        for (int i = 0; i < 4; i++) { pk[i] = Kg[tid + i * 256]; pv[i] = Vg[tid + i * 256]; }
    }

    for (int it = 0; it < cnt; it++) {
        __syncthreads();
        #pragma unroll
        for (int i = 0; i < 4; i++) {
            int idx = tid + i * 256;
            int row = idx >> 4, c4 = (idx & 15) * 4;
            float4 kv = pk[i];
            *(__half2*)&Ks[row * LDH + c4]     = __floats2half2_rn(kv.x, kv.y);
            *(__half2*)&Ks[row * LDH + c4 + 2] = __floats2half2_rn(kv.z, kv.w);
            float4 vv = pv[i];
            Vt[(c4 + 0) * LDH + row] = __float2half_rn(vv.x);
            Vt[(c4 + 1) * LDH + row] = __float2half_rn(vv.y);
            Vt[(c4 + 2) * LDH + row] = __float2half_rn(vv.z);
            Vt[(c4 + 3) * LDH + row] = __float2half_rn(vv.w);
        }
        __syncthreads();
        if (it + 1 < cnt) {
            int kb = list[it + 1];
            const float4* Kg = (const float4*)(g_k + (bh * LL + kb * BLKK) * DD);
            const float4* Vg = (const float4*)(g_v + (bh * LL + kb * BLKK) * DD);
            #pragma unroll
            for (int i = 0; i < 4; i++) { pk[i] = Kg[tid + i * 256]; pv[i] = Vg[tid + i * 256]; }
        }

        float sc[8][4];
        #pragma unroll
        for (int nt = 0; nt < 8; nt++) { sc[nt][0]=0.f; sc[nt][1]=0.f; sc[nt][2]=0.f; sc[nt][3]=0.f; }
        #pragma unroll
        for (int kc = 0; kc < 4; kc++) {
            #pragma unroll
            for (int nt = 0; nt < 8; nt++) {
                unsigned b0 = *(const unsigned*)&Ks[(nt * 8 + g) * LDH + kc * 16 + 2 * t];
                unsigned b1 = *(const unsigned*)&Ks[(nt * 8 + g) * LDH + kc * 16 + 2 * t + 8];
                MMA_F16(sc[nt], qa[kc][0], qa[kc][1], qa[kc][2], qa[kc][3], b0, b1);
            }
        }

        float mx0 = -CUDART_INF_F, mx1 = -CUDART_INF_F;
        #pragma unroll
        for (int nt = 0; nt < 8; nt++) {
            mx0 = fmaxf(mx0, fmaxf(sc[nt][0], sc[nt][1]));
            mx1 = fmaxf(mx1, fmaxf(sc[nt][2], sc[nt][3]));
        }
        mx0 = fmaxf(mx0, __shfl_xor_sync(0xffffffffu, mx0, 1));
        mx0 = fmaxf(mx0, __shfl_xor_sync(0xffffffffu, mx0, 2));
        mx1 = fmaxf(mx1, __shfl_xor_sync(0xffffffffu, mx1, 1));
        mx1 = fmaxf(mx1, __shfl_xor_sync(0xffffffffu, mx1, 2));
        float nm0 = fmaxf(m0, mx0);
        float nm1 = fmaxf(m1, mx1);
        float f0 = __expf(m0 - nm0);
        float f1 = __expf(m1 - nm1);
        #pragma unroll
        for (int dt = 0; dt < 8; dt++) {
            oacc[dt][0] *= f0; oacc[dt][1] *= f0;
            oacc[dt][2] *= f1; oacc[dt][3] *= f1;
        }
        l0 *= f0; l1 *= f1;
        m0 = nm0; m1 = nm1;

        float s0 = 0.f, s1 = 0.f;
        __half* p0 = &Ps[(w * 16 + g) * LDH];
        __half* p1 = &Ps[(w * 16 + g + 8) * LDH];
        #pragma unroll
        for (int nt = 0; nt < 8; nt++) {
            float e00 = __expf(sc[nt][0] - nm0);
            float e01 = __expf(sc[nt][1] - nm0);
            float e10 = __expf(sc[nt][2] - nm1);
            float e11 = __expf(sc[nt][3] - nm1);
            s0 += e00 + e01; s1 += e10 + e11;
            *(__half2*)&p0[nt * 8 + 2 * t] = __floats2half2_rn(e00, e01);
            *(__half2*)&p1[nt * 8 + 2 * t] = __floats2half2_rn(e10, e11);
        }
        s0 += __shfl_xor_sync(0xffffffffu, s0, 1);
        s0 += __shfl_xor_sync(0xffffffffu, s0, 2);
        s1 += __shfl_xor_sync(0xffffffffu, s1, 1);
        s1 += __shfl_xor_sync(0xffffffffu, s1, 2);
        l0 += s0; l1 += s1;
        __syncwarp();

        #pragma unroll
        for (int kc = 0; kc < 4; kc++) {
            unsigned a0 = *(const unsigned*)&Ps[(w * 16 + g) * LDH + kc * 16 + 2 * t];
            unsigned a1 = *(const unsigned*)&Ps[(w * 16 + g + 8) * LDH + kc * 16 + 2 * t];
            unsigned a2 = *(const unsigned*)&Ps[(w * 16 + g) * LDH + kc * 16 + 2 * t + 8];
            unsigned a3 = *(const unsigned*)&Ps[(w * 16 + g + 8) * LDH + kc * 16 + 2 * t + 8];
            #pragma unroll
            for (int dt = 0; dt < 8; dt++) {
                unsigned b0 = *(const unsigned*)&Vt[(dt * 8 + g) * LDH + kc * 16 + 2 * t];
                unsigned b1 = *(const unsigned*)&Vt[(dt * 8 + g) * LDH + kc * 16 + 2 * t + 8];
                MMA_F16(oacc[dt], a0, a1, a2, a3, b0, b1);
            }
        }
        __syncwarp();
    }

    float inv0 = 1.0f / l0;
    float inv1 = 1.0f / l1;
    int b = bh >> 3, h = bh & 7;
    int grow = qb * 128 + w * 16 + g;
    float* o0 = g_ot + (b * LL + grow) * CC + h * DD;
    float* o1 = o0 + 8 * CC;
    #pragma unroll
    for (int dt = 0; dt < 8; dt++) {
        *(float2*)&o0[dt * 8 + 2 * t] = make_float2(oacc[dt][0] * inv0, oacc[dt][1] * inv0);
        *(float2*)&o1[dt * 8 + 2 * t] = make_float2(oacc[dt][2] * inv1, oacc[dt][3] * inv1);
    }
}

extern "C" void kernel_launch(void* const* d_in, const int* in_sizes, int n_in,
                              void* d_out, int out_size) {
    const float* x     = (const float*)d_in[0];
    const float* Wqkv  = (const float*)d_in[1];
    const float* bqkv  = (const float*)d_in[2];
    const float* Wproj = (const float*)d_in[3];
    const float* bproj = (const float*)d_in[4];
    float* out = (float*)d_out;

    dim3 g1(24, 64);                       // N=1536/64, M=4096/64
    gemm_f16<3 * CC, true><<<g1, 128>>>(x, Wqkv, bqkv, nullptr);

    block_meta<BLKQ, true><<<BB * HH * NQ, 128>>>(NQ);
    block_meta<BLKK, false><<<BB * HH * NK, 128>>>(NK);

    mask_kernel<<<BB * HH, 512>>>();

    const int smem = 256 * LDH * sizeof(__half);   // 36864 B
    cudaFuncSetAttribute(attn_kernel, cudaFuncAttributeMaxDynamicSharedMemorySize, smem);
    dim3 ga(NQ, BB * HH);
    attn_kernel<<<ga, 256, smem>>>();

    dim3 g2(8, 64);                        // N=512/64, M=4096/64
    gemm_f16<CC, false><<<g2, 128>>>(nullptr, Wproj, bproj, out);
}

// round 14
// speedup vs baseline: 1.3372x; 1.0214x over previous
#include <cuda_runtime.h>
#include <cuda_fp16.h>
#include <math_constants.h>

#define BB 2
#define HH 8
#define LL 2048
#define DD 64
#define CC 512
#define NQ 16
#define NK 32
#define BLKQ 128
#define BLKK 64

// ---------------- scratch (no allocations allowed) ----------------
__device__ float g_q[BB*HH*LL*DD];
__device__ float g_k[BB*HH*LL*DD];
__device__ float g_v[BB*HH*LL*DD];
__device__ float g_qm[BB*HH*NQ*DD];
__device__ float g_km[BB*HH*NK*DD];
__device__ float g_qsim[BB*HH*NQ];
__device__ float g_ksim[BB*HH*NK];
__device__ int   g_cnt[BB*HH*NQ];
__device__ int   g_list[BB*HH*NQ*NK];
__device__ float g_ot[BB*LL*CC];

__device__ __forceinline__ unsigned pkh2(float a, float b) {
    __half2 h = __floats2half2_rn(a, b);
    return *(unsigned*)&h;
}

#define MMA_F16(c, a0, a1, a2, a3, b0, b1)                                    \
    asm volatile(                                                             \
        "mma.sync.aligned.m16n8k16.row.col.f32.f16.f16.f32 "                  \
        "{%0,%1,%2,%3},{%4,%5,%6,%7},{%8,%9},{%0,%1,%2,%3};"                  \
        : "+f"((c)[0]), "+f"((c)[1]), "+f"((c)[2]), "+f"((c)[3])              \
        : "r"(a0), "r"(a1), "r"(a2), "r"(a3), "r"(b0), "r"(b1))

// ---------------- split-fp16 tensor-core GEMM, 128x128 CTA tile ----------------
// 256 threads, 8 warps in a 2(m) x 4(n) grid; each warp computes 64x32.
// k-chunk 32, register prefetch of next chunk. 2-term hi/lo fp16 split
// (hh + hl + lh, fp32 accum) => near-fp32 accuracy (residual ~2^-20).
// A staged [m][k]; B staged transposed [n][k] (contiguous half2 fragments).
#define LDA 40
#define LDB 42
template<int N, bool QKV>
__global__ void __launch_bounds__(256) gemm_f16(const float* __restrict__ Ain,
                                                const float* __restrict__ W,
                                                const float* __restrict__ bias,
                                                float* __restrict__ out) {
    __shared__ __half Ahi[128][LDA], Alo[128][LDA];
    __shared__ __half Bhi[128][LDB], Blo[128][LDB];
    const float* __restrict__ A = QKV ? Ain : (const float*)g_ot;
    const int K = CC;
    int tid = threadIdx.x;
    int w = tid >> 5, lane = tid & 31;
    int g = lane >> 2, t = lane & 3;
    int wm = (w & 1) * 64, wn = (w >> 1) * 32;
    int m0 = blockIdx.y * 128, n0 = blockIdx.x * 128;

    int arow = tid >> 3, ac4 = (tid & 7) * 4;    // A tile 128x32 floats (idx row = idx>>3)
    int bkrow = tid >> 5, bnc4 = (tid & 31) * 4; // W tile 32x128 floats

    float4 pa[4], pb[4];
    #pragma unroll
    for (int i = 0; i < 4; i++) {
        pa[i] = *(const float4*)&A[(m0 + arow + i * 32) * K + ac4];
        pb[i] = *(const float4*)&W[(bkrow + i * 8) * N + n0 + bnc4];
    }

    float acc[4][4][4] = {};

    for (int k0 = 0; k0 < K; k0 += 32) {
        __syncthreads();
        #pragma unroll
        for (int i = 0; i < 4; i++) {
            // A: hi/lo split, [m][k]
            float4 v = pa[i];
            int row = arow + i * 32;
            __half h0 = __float2half_rn(v.x), h1 = __float2half_rn(v.y);
            __half h2 = __float2half_rn(v.z), h3 = __float2half_rn(v.w);
            Ahi[row][ac4+0] = h0; Ahi[row][ac4+1] = h1;
            Ahi[row][ac4+2] = h2; Ahi[row][ac4+3] = h3;
            Alo[row][ac4+0] = __float2half_rn(v.x - __half2float(h0));
            Alo[row][ac4+1] = __float2half_rn(v.y - __half2float(h1));
            Alo[row][ac4+2] = __float2half_rn(v.z - __half2float(h2));
            Alo[row][ac4+3] = __float2half_rn(v.w - __half2float(h3));
            // B: hi/lo split, transposed to [n][k]
            v = pb[i];
            int krow = bkrow + i * 8;
            h0 = __float2half_rn(v.x); h1 = __float2half_rn(v.y);
            h2 = __float2half_rn(v.z); h3 = __float2half_rn(v.w);
            Bhi[bnc4+0][krow] = h0; Bhi[bnc4+1][krow] = h1;
            Bhi[bnc4+2][krow] = h2; Bhi[bnc4+3][krow] = h3;
            Blo[bnc4+0][krow] = __float2half_rn(v.x - __half2float(h0));
            Blo[bnc4+1][krow] = __float2half_rn(v.y - __half2float(h1));
            Blo[bnc4+2][krow] = __float2half_rn(v.z - __half2float(h2));
            Blo[bnc4+3][krow] = __float2half_rn(v.w - __half2float(h3));
        }
        __syncthreads();
        if (k0 + 32 < K) {
            #pragma unroll
            for (int i = 0; i < 4; i++) {
                pa[i] = *(const float4*)&A[(m0 + arow + i * 32) * K + k0 + 32 + ac4];
                pb[i] = *(const float4*)&W[(k0 + 32 + bkrow + i * 8) * N + n0 + bnc4];
            }
        }
        #pragma unroll
        for (int kc = 0; kc < 2; kc++) {
            int c = kc * 16 + 2 * t;
            unsigned ahi[4][4], alo[4][4];
            #pragma unroll
            for (int mf = 0; mf < 4; mf++) {
                int r0 = wm + mf * 16 + g;
                ahi[mf][0] = *(const unsigned*)&Ahi[r0][c];
                ahi[mf][1] = *(const unsigned*)&Ahi[r0+8][c];
                ahi[mf][2] = *(const unsigned*)&Ahi[r0][c+8];
                ahi[mf][3] = *(const unsigned*)&Ahi[r0+8][c+8];
                alo[mf][0] = *(const unsigned*)&Alo[r0][c];
                alo[mf][1] = *(const unsigned*)&Alo[r0+8][c];
                alo[mf][2] = *(const unsigned*)&Alo[r0][c+8];
                alo[mf][3] = *(const unsigned*)&Alo[r0+8][c+8];
            }
            #pragma unroll
            for (int nt = 0; nt < 4; nt++) {
                int nr = wn + nt * 8 + g;
                unsigned bh0 = *(const unsigned*)&Bhi[nr][c];
                unsigned bh1 = *(const unsigned*)&Bhi[nr][c+8];
                unsigned bl0 = *(const unsigned*)&Blo[nr][c];
                unsigned bl1 = *(const unsigned*)&Blo[nr][c+8];
                #pragma unroll
                for (int mf = 0; mf < 4; mf++) {
                    MMA_F16(acc[mf][nt], ahi[mf][0], ahi[mf][1], ahi[mf][2], ahi[mf][3], bh0, bh1);
                    MMA_F16(acc[mf][nt], ahi[mf][0], ahi[mf][1], ahi[mf][2], ahi[mf][3], bl0, bl1);
                    MMA_F16(acc[mf][nt], alo[mf][0], alo[mf][1], alo[mf][2], alo[mf][3], bh0, bh1);
                }
            }
        }
    }

    #pragma unroll
    for (int mf = 0; mf < 4; mf++) {
        #pragma unroll
        for (int rr = 0; rr < 2; rr++) {
            int m = m0 + wm + mf * 16 + g + rr * 8;
            #pragma unroll
            for (int nt = 0; nt < 4; nt++) {
                #pragma unroll
                for (int cc = 0; cc < 2; cc++) {
                    int j = n0 + wn + nt * 8 + 2 * t + cc;
                    float val = acc[mf][nt][rr * 2 + cc] + bias[j];
                    if (QKV) {
                        int b = m >> 11, l = m & 2047;
                        int ty = j >> 9, h = (j >> 6) & 7, d = j & 63;
                        float* dst = (ty == 0) ? g_q : (ty == 1) ? g_k : g_v;
                        dst[(((b * HH + h) * LL) + l) * DD + d] = val;
                    } else {
                        out[m * N + j] = val;
                    }
                }
            }
        }
    }
}

// ---------------- block means + min-cosine ----------------
template<int BLK, bool ISQ>
__global__ void __launch_bounds__(128) block_meta(int nb) {
    __shared__ float tile[BLK * 65];
    __shared__ float mean[64];
    __shared__ float red[128];
    __shared__ float nm_s;
    const float* t = ISQ ? g_q : g_k;
    float* mout = ISQ ? g_qm : g_km;
    float* simout = ISQ ? g_qsim : g_ksim;
    int blkid = blockIdx.x % nb;
    int bh = blockIdx.x / nb;
    const float* base = t + (bh * LL + blkid * BLK) * DD;
    int tid = threadIdx.x;
    for (int i = tid; i < BLK * DD; i += 128) {
        int r = i >> 6, d = i & 63;
        tile[r * 65 + d] = base[i];
    }
    __syncthreads();
    if (tid < 64) {
        float s = 0.f;
        for (int r = 0; r < BLK; r++) s += tile[r * 65 + tid];
        s *= (1.0f / BLK);
        mean[tid] = s;
        mout[blockIdx.x * 64 + tid] = s;
    }
    __syncthreads();
    if (tid == 0) {
        float s = 0.f;
        for (int d = 0; d < 64; d++) s += mean[d] * mean[d];
        nm_s = sqrtf(s) + 1e-6f;
    }
    __syncthreads();
    float mycos = CUDART_INF_F;
    if (tid < BLK) {
        float dot = 0.f, nr = 0.f;
        for (int d = 0; d < 64; d++) {
            float xv = tile[tid * 65 + d];
            dot += xv * mean[d];
            nr += xv * xv;
        }
        mycos = dot / ((sqrtf(nr) + 1e-6f) * nm_s);
    }
    red[tid] = mycos;
    __syncthreads();
    for (int s = 64; s > 0; s >>= 1) {
        if (tid < s) red[tid] = fminf(red[tid], red[tid + s]);
        __syncthreads();
    }
    if (tid == 0) simout[blockIdx.x] = red[0];
}

// ---------------- pooled softmax + CDF keep mask -> compacted kept-block lists ----------------
__global__ void __launch_bounds__(512) mask_kernel() {
    __shared__ float qm_s[NQ * DD];
    __shared__ float km_s[NK * DD];
    __shared__ float pooled[NQ][NK + 1];
    __shared__ float ksim_s[NK];
    int bh = blockIdx.x;
    int tid = threadIdx.x;
    for (int i = tid; i < NQ * DD; i += 512) qm_s[i] = g_qm[bh * NQ * DD + i];
    for (int i = tid; i < NK * DD; i += 512) km_s[i] = g_km[bh * NK * DD + i];
    if (tid < NK) ksim_s[tid] = g_ksim[bh * NK + tid];
    __syncthreads();
    {
        int qi = tid >> 5, j = tid & 31;
        const float* qv = &qm_s[qi * DD];
        const float* kv = &km_s[j * DD];
        float dot = 0.f;
        #pragma unroll
        for (int d = 0; d < DD; d++) dot += qv[d] * kv[d];
        pooled[qi][j] = dot * 0.125f;
    }
    __syncthreads();
    int w = tid >> 5;
    int lane = tid & 31;
    float v = pooled[w][lane];
    float mx = v;
    #pragma unroll
    for (int s = 16; s > 0; s >>= 1) mx = fmaxf(mx, __shfl_xor_sync(0xffffffffu, mx, s));
    float p = expf(v - mx);
    float sum = p;
    #pragma unroll
    for (int s = 16; s > 0; s >>= 1) sum += __shfl_xor_sync(0xffffffffu, sum, s);
    p /= sum;
    float sv = p;
    int si = lane;
    #pragma unroll
    for (int k = 2; k <= 32; k <<= 1) {
        #pragma unroll
        for (int j = k >> 1; j > 0; j >>= 1) {
            float ov = __shfl_xor_sync(0xffffffffu, sv, j);
            int   oi = __shfl_xor_sync(0xffffffffu, si, j);
            bool iprecede = (sv > ov) || (sv == ov && si < oi);
            bool lower = ((lane & j) == 0);
            bool dir = ((lane & k) == 0);
            bool keep_mine = ((lower == iprecede) == dir);
            if (!keep_mine) { sv = ov; si = oi; }
        }
    }
    float csum = sv;
    #pragma unroll
    for (int s = 1; s < 32; s <<= 1) {
        float t = __shfl_up_sync(0xffffffffu, csum, s);
        if (lane >= s) csum += t;
    }
    bool kept_sorted = (csum - sv) < 0.98f;
    unsigned keepmask = __reduce_or_sync(0xffffffffu, kept_sorted ? (1u << si) : 0u);
    bool qself = g_qsim[bh * NQ + w] > 0.6f;
    bool kself = ksim_s[lane] > 0.6f;
    bool fin = ((keepmask >> lane) & 1u) || !qself || !kself;
    unsigned fmask = __ballot_sync(0xffffffffu, fin);
    int pos = __popc(fmask & ((1u << lane) - 1u));
    int rowid = bh * NQ + w;
    if (fin) g_list[rowid * NK + pos] = lane;
    if (lane == 0) g_cnt[rowid] = __popc(fmask);
}

// ---------------- fp16 tensor-core flash attention (m16n8k16) ----------------
#define LDH 72
__global__ void __launch_bounds__(256) attn_kernel() {
    extern __shared__ __half smh[];
    __half* Ks = smh;               // [64 keys][LDH]
    __half* Vt = smh + 64 * LDH;    // [64 d][LDH]
    __half* Ps = smh + 128 * LDH;   // [128 q][LDH]

    int bh = blockIdx.y;
    int qb = blockIdx.x;
    int tid = threadIdx.x;
    int w = tid >> 5;
    int lane = tid & 31;
    int g = lane >> 2;
    int t = lane & 3;

    unsigned qa[4][4];
    {
        const float* q0 = g_q + (bh * LL + qb * 128 + w * 16 + g) * DD;
        const float* q1 = q0 + 8 * DD;
        #pragma unroll
        for (int kc = 0; kc < 4; kc++) {
            int c = kc * 16 + 2 * t;
            qa[kc][0] = pkh2(q0[c] * 0.125f,     q0[c + 1] * 0.125f);
            qa[kc][1] = pkh2(q1[c] * 0.125f,     q1[c + 1] * 0.125f);
            qa[kc][2] = pkh2(q0[c + 8] * 0.125f, q0[c + 9] * 0.125f);
            qa[kc][3] = pkh2(q1[c + 8] * 0.125f, q1[c + 9] * 0.125f);
        }
    }

    float oacc[8][4];
    #pragma unroll
    for (int dt = 0; dt < 8; dt++) { oacc[dt][0]=0.f; oacc[dt][1]=0.f; oacc[dt][2]=0.f; oacc[dt][3]=0.f; }
    float m0 = -CUDART_INF_F, m1 = -CUDART_INF_F;
    float l0 = 0.f, l1 = 0.f;

    int cnt = g_cnt[bh * NQ + qb];
    const int* __restrict__ list = g_list + (bh * NQ + qb) * NK;

    float4 pk[4], pv[4];
    if (cnt > 0) {
        int kb = list[0];
        const float4* Kg = (const float4*)(g_k + (bh * LL + kb * BLKK) * DD);
        const float4* Vg = (const float4*)(g_v + (bh * LL + kb * BLKK) * DD);
        #pragma unroll
        for (int i = 0; i < 4; i++) { pk[i] = Kg[tid + i * 256]; pv[i] = Vg[tid + i * 256]; }
    }

    for (int it = 0; it < cnt; it++) {
        __syncthreads();
        #pragma unroll
        for (int i = 0; i < 4; i++) {
            int idx = tid + i * 256;
            int row = idx >> 4, c4 = (idx & 15) * 4;
            float4 kv = pk[i];
            *(__half2*)&Ks[row * LDH + c4]     = __floats2half2_rn(kv.x, kv.y);
            *(__half2*)&Ks[row * LDH + c4 + 2] = __floats2half2_rn(kv.z, kv.w);
            float4 vv = pv[i];
            Vt[(c4 + 0) * LDH + row] = __float2half_rn(vv.x);
            Vt[(c4 + 1) * LDH + row] = __float2half_rn(vv.y);
            Vt[(c4 + 2) * LDH + row] = __float2half_rn(vv.z);
            Vt[(c4 + 3) * LDH + row] = __float2half_rn(vv.w);
        }
        __syncthreads();
        if (it + 1 < cnt) {
            int kb = list[it + 1];
            const float4* Kg = (const float4*)(g_k + (bh * LL + kb * BLKK) * DD);
            const float4* Vg = (const float4*)(g_v + (bh * LL + kb * BLKK) * DD);
            #pragma unroll
            for (int i = 0; i < 4; i++) { pk[i] = Kg[tid + i * 256]; pv[i] = Vg[tid + i * 256]; }
        }

        float sc[8][4];
        #pragma unroll
        for (int nt = 0; nt < 8; nt++) { sc[nt][0]=0.f; sc[nt][1]=0.f; sc[nt][2]=0.f; sc[nt][3]=0.f; }
        #pragma unroll
        for (int kc = 0; kc < 4; kc++) {
            #pragma unroll
            for (int nt = 0; nt < 8; nt++) {
                unsigned b0 = *(const unsigned*)&Ks[(nt * 8 + g) * LDH + kc * 16 + 2 * t];
                unsigned b1 = *(const unsigned*)&Ks[(nt * 8 + g) * LDH + kc * 16 + 2 * t + 8];
                MMA_F16(sc[nt], qa[kc][0], qa[kc][1], qa[kc][2], qa[kc][3], b0, b1);
            }
        }

        float mx0 = -CUDART_INF_F, mx1 = -CUDART_INF_F;
        #pragma unroll
        for (int nt = 0; nt < 8; nt++) {
            mx0 = fmaxf(mx0, fmaxf(sc[nt][0], sc[nt][1]));
            mx1 = fmaxf(mx1, fmaxf(sc[nt][2], sc[nt][3]));
        }
        mx0 = fmaxf(mx0, __shfl_xor_sync(0xffffffffu, mx0, 1));
        mx0 = fmaxf(mx0, __shfl_xor_sync(0xffffffffu, mx0, 2));
        mx1 = fmaxf(mx1, __shfl_xor_sync(0xffffffffu, mx1, 1));
        mx1 = fmaxf(mx1, __shfl_xor_sync(0xffffffffu, mx1, 2));
        float nm0 = fmaxf(m0, mx0);
        float nm1 = fmaxf(m1, mx1);
        float f0 = __expf(m0 - nm0);
        float f1 = __expf(m1 - nm1);
        #pragma unroll
        for (int dt = 0; dt < 8; dt++) {
            oacc[dt][0] *= f0; oacc[dt][1] *= f0;
            oacc[dt][2] *= f1; oacc[dt][3] *= f1;
        }
        l0 *= f0; l1 *= f1;
        m0 = nm0; m1 = nm1;

        float s0 = 0.f, s1 = 0.f;
        __half* p0 = &Ps[(w * 16 + g) * LDH];
        __half* p1 = &Ps[(w * 16 + g + 8) * LDH];
        #pragma unroll
        for (int nt = 0; nt < 8; nt++) {
            float e00 = __expf(sc[nt][0] - nm0);
            float e01 = __expf(sc[nt][1] - nm0);
            float e10 = __expf(sc[nt][2] - nm1);
            float e11 = __expf(sc[nt][3] - nm1);
            s0 += e00 + e01; s1 += e10 + e11;
            *(__half2*)&p0[nt * 8 + 2 * t] = __floats2half2_rn(e00, e01);
            *(__half2*)&p1[nt * 8 + 2 * t] = __floats2half2_rn(e10, e11);
        }
        s0 += __shfl_xor_sync(0xffffffffu, s0, 1);
        s0 += __shfl_xor_sync(0xffffffffu, s0, 2);
        s1 += __shfl_xor_sync(0xffffffffu, s1, 1);
        s1 += __shfl_xor_sync(0xffffffffu, s1, 2);
        l0 += s0; l1 += s1;
        __syncwarp();

        #pragma unroll
        for (int kc = 0; kc < 4; kc++) {
            unsigned a0 = *(const unsigned*)&Ps[(w * 16 + g) * LDH + kc * 16 + 2 * t];
            unsigned a1 = *(const unsigned*)&Ps[(w * 16 + g + 8) * LDH + kc * 16 + 2 * t];
            unsigned a2 = *(const unsigned*)&Ps[(w * 16 + g) * LDH + kc * 16 + 2 * t + 8];
            unsigned a3 = *(const unsigned*)&Ps[(w * 16 + g + 8) * LDH + kc * 16 + 2 * t + 8];
            #pragma unroll
            for (int dt = 0; dt < 8; dt++) {
                unsigned b0 = *(const unsigned*)&Vt[(dt * 8 + g) * LDH + kc * 16 + 2 * t];
                unsigned b1 = *(const unsigned*)&Vt[(dt * 8 + g) * LDH + kc * 16 + 2 * t + 8];
                MMA_F16(oacc[dt], a0, a1, a2, a3, b0, b1);
            }
        }
        __syncwarp();
    }

    float inv0 = 1.0f / l0;
    float inv1 = 1.0f / l1;
    int b = bh >> 3, h = bh & 7;
    int grow = qb * 128 + w * 16 + g;
    float* o0 = g_ot + (b * LL + grow) * CC + h * DD;
    float* o1 = o0 + 8 * CC;
    #pragma unroll
    for (int dt = 0; dt < 8; dt++) {
        *(float2*)&o0[dt * 8 + 2 * t] = make_float2(oacc[dt][0] * inv0, oacc[dt][1] * inv0);
        *(float2*)&o1[dt * 8 + 2 * t] = make_float2(oacc[dt][2] * inv1, oacc[dt][3] * inv1);
    }
}

extern "C" void kernel_launch(void* const* d_in, const int* in_sizes, int n_in,
                              void* d_out, int out_size) {
    const float* x     = (const float*)d_in[0];
    const float* Wqkv  = (const float*)d_in[1];
    const float* bqkv  = (const float*)d_in[2];
    const float* Wproj = (const float*)d_in[3];
    const float* bproj = (const float*)d_in[4];
    float* out = (float*)d_out;

    dim3 g1(12, 32);                       // N=1536/128, M=4096/128
    gemm_f16<3 * CC, true><<<g1, 256>>>(x, Wqkv, bqkv, nullptr);

    block_meta<BLKQ, true><<<BB * HH * NQ, 128>>>(NQ);
    block_meta<BLKK, false><<<BB * HH * NK, 128>>>(NK);

    mask_kernel<<<BB * HH, 512>>>();

    const int smem = 256 * LDH * sizeof(__half);   // 36864 B
    cudaFuncSetAttribute(attn_kernel, cudaFuncAttributeMaxDynamicSharedMemorySize, smem);
    dim3 ga(NQ, BB * HH);
    attn_kernel<<<ga, 256, smem>>>();

    dim3 g2(4, 32);                        // N=512/128, M=4096/128
    gemm_f16<CC, false><<<g2, 256>>>(nullptr, Wproj, bproj, out);
}

// round 16
// speedup vs baseline: 1.3670x; 1.0223x over previous
#include <cuda_runtime.h>
#include <cuda_fp16.h>
#include <math_constants.h>

#define BB 2
#define HH 8
#define LL 2048
#define DD 64
#define CC 512
#define NQ 16
#define NK 32
#define BLKQ 128
#define BLKK 64

// ---------------- scratch (no allocations allowed) ----------------
__device__ float g_q[BB*HH*LL*DD];
__device__ float g_k[BB*HH*LL*DD];
__device__ float g_v[BB*HH*LL*DD];
__device__ float g_qm[BB*HH*NQ*DD];
__device__ float g_km[BB*HH*NK*DD];
__device__ float g_qsim[BB*HH*NQ];
__device__ float g_ksim[BB*HH*NK];
__device__ int   g_cnt[BB*HH*NQ];
__device__ int   g_list[BB*HH*NQ*NK];
__device__ float g_ot[BB*LL*CC];

__device__ __forceinline__ unsigned pkh2(float a, float b) {
    __half2 h = __floats2half2_rn(a, b);
    return *(unsigned*)&h;
}

#define MMA_F16(c, a0, a1, a2, a3, b0, b1)                                    \
    asm volatile(                                                             \
        "mma.sync.aligned.m16n8k16.row.col.f32.f16.f16.f32 "                  \
        "{%0,%1,%2,%3},{%4,%5,%6,%7},{%8,%9},{%0,%1,%2,%3};"                  \
        : "+f"((c)[0]), "+f"((c)[1]), "+f"((c)[2]), "+f"((c)[3])              \
        : "r"(a0), "r"(a1), "r"(a2), "r"(a3), "r"(b0), "r"(b1))

// ---------------- split-fp16 GEMM, 128x128 tile, DOUBLE-BUFFERED smem ----------------
// 256 threads, 8 warps (2m x 4n), each warp 64x32. k-chunk 32, 16 chunks.
// Loop body: stage(chunk i+1 -> buf^1) ; prefetch(chunk i+2 -> regs) ; mma(buf) ; sync.
// Staging ALU + LDG latency hide behind the 96-mma block.
#define LDA 40
#define LDB 42
#define ASZ (128 * LDA)
#define BSZ (128 * LDB)
#define GBUF (2 * ASZ + 2 * BSZ)
#define GSMEM (2 * GBUF * (int)sizeof(__half))
template<int N, bool QKV>
__global__ void __launch_bounds__(256) gemm_f16(const float* __restrict__ Ain,
                                                const float* __restrict__ W,
                                                const float* __restrict__ bias,
                                                float* __restrict__ out) {
    extern __shared__ __half gsm[];
    const float* __restrict__ A = QKV ? Ain : (const float*)g_ot;
    const int K = CC;
    const int NCH = K / 32;
    int tid = threadIdx.x;
    int w = tid >> 5, lane = tid & 31;
    int g = lane >> 2, t = lane & 3;
    int wm = (w & 1) * 64, wn = (w >> 1) * 32;
    int m0 = blockIdx.y * 128, n0 = blockIdx.x * 128;

    int arow = tid >> 3, ac4 = (tid & 7) * 4;    // A tile 128x32 floats
    int bkrow = tid >> 5, bnc4 = (tid & 31) * 4; // W tile 32x128 floats

    float4 pa[4], pb[4];

    auto loadchunk = [&](int c) {
        #pragma unroll
        for (int i = 0; i < 4; i++) {
            pa[i] = *(const float4*)&A[(m0 + arow + i * 32) * K + c * 32 + ac4];
            pb[i] = *(const float4*)&W[(c * 32 + bkrow + i * 8) * N + n0 + bnc4];
        }
    };
    auto stage = [&](int buf) {
        __half* Ahi = gsm + buf * GBUF;
        __half* Alo = Ahi + ASZ;
        __half* Bhi = Alo + ASZ;
        __half* Blo = Bhi + BSZ;
        #pragma unroll
        for (int i = 0; i < 4; i++) {
            float4 v = pa[i];
            int row = arow + i * 32;
            __half h0 = __float2half_rn(v.x), h1 = __float2half_rn(v.y);
            __half h2 = __float2half_rn(v.z), h3 = __float2half_rn(v.w);
            Ahi[row*LDA + ac4+0] = h0; Ahi[row*LDA + ac4+1] = h1;
            Ahi[row*LDA + ac4+2] = h2; Ahi[row*LDA + ac4+3] = h3;
            Alo[row*LDA + ac4+0] = __float2half_rn(v.x - __half2float(h0));
            Alo[row*LDA + ac4+1] = __float2half_rn(v.y - __half2float(h1));
            Alo[row*LDA + ac4+2] = __float2half_rn(v.z - __half2float(h2));
            Alo[row*LDA + ac4+3] = __float2half_rn(v.w - __half2float(h3));
            v = pb[i];
            int krow = bkrow + i * 8;
            h0 = __float2half_rn(v.x); h1 = __float2half_rn(v.y);
            h2 = __float2half_rn(v.z); h3 = __float2half_rn(v.w);
            Bhi[(bnc4+0)*LDB + krow] = h0; Bhi[(bnc4+1)*LDB + krow] = h1;
            Bhi[(bnc4+2)*LDB + krow] = h2; Bhi[(bnc4+3)*LDB + krow] = h3;
            Blo[(bnc4+0)*LDB + krow] = __float2half_rn(v.x - __half2float(h0));
            Blo[(bnc4+1)*LDB + krow] = __float2half_rn(v.y - __half2float(h1));
            Blo[(bnc4+2)*LDB + krow] = __float2half_rn(v.z - __half2float(h2));
            Blo[(bnc4+3)*LDB + krow] = __float2half_rn(v.w - __half2float(h3));
        }
    };

    float acc[4][4][4] = {};

    loadchunk(0);
    stage(0);
    loadchunk(1);
    __syncthreads();

    for (int ci = 0; ci < NCH; ci++) {
        int cur = ci & 1;
        if (ci + 1 < NCH) stage(cur ^ 1);     // regs hold chunk ci+1
        if (ci + 2 < NCH) loadchunk(ci + 2);  // prefetch, consumed next iter
        const __half* Ahi = gsm + cur * GBUF;
        const __half* Alo = Ahi + ASZ;
        const __half* Bhi = Alo + ASZ;
        const __half* Blo = Bhi + BSZ;
        #pragma unroll
        for (int kc = 0; kc < 2; kc++) {
            int c = kc * 16 + 2 * t;
            unsigned ahi[4][4], alo[4][4];
            #pragma unroll
            for (int mf = 0; mf < 4; mf++) {
                int r0 = wm + mf * 16 + g;
                ahi[mf][0] = *(const unsigned*)&Ahi[r0*LDA + c];
                ahi[mf][1] = *(const unsigned*)&Ahi[(r0+8)*LDA + c];
                ahi[mf][2] = *(const unsigned*)&Ahi[r0*LDA + c+8];
                ahi[mf][3] = *(const unsigned*)&Ahi[(r0+8)*LDA + c+8];
                alo[mf][0] = *(const unsigned*)&Alo[r0*LDA + c];
                alo[mf][1] = *(const unsigned*)&Alo[(r0+8)*LDA + c];
                alo[mf][2] = *(const unsigned*)&Alo[r0*LDA + c+8];
                alo[mf][3] = *(const unsigned*)&Alo[(r0+8)*LDA + c+8];
            }
            #pragma unroll
            for (int nt = 0; nt < 4; nt++) {
                int nr = wn + nt * 8 + g;
                unsigned bh0 = *(const unsigned*)&Bhi[nr*LDB + c];
                unsigned bh1 = *(const unsigned*)&Bhi[nr*LDB + c+8];
                unsigned bl0 = *(const unsigned*)&Blo[nr*LDB + c];
                unsigned bl1 = *(const unsigned*)&Blo[nr*LDB + c+8];
                #pragma unroll
                for (int mf = 0; mf < 4; mf++) {
                    MMA_F16(acc[mf][nt], ahi[mf][0], ahi[mf][1], ahi[mf][2], ahi[mf][3], bh0, bh1);
                    MMA_F16(acc[mf][nt], ahi[mf][0], ahi[mf][1], ahi[mf][2], ahi[mf][3], bl0, bl1);
                    MMA_F16(acc[mf][nt], alo[mf][0], alo[mf][1], alo[mf][2], alo[mf][3], bh0, bh1);
                }
            }
        }
        __syncthreads();
    }

    #pragma unroll
    for (int mf = 0; mf < 4; mf++) {
        #pragma unroll
        for (int rr = 0; rr < 2; rr++) {
            int m = m0 + wm + mf * 16 + g + rr * 8;
            #pragma unroll
            for (int nt = 0; nt < 4; nt++) {
                #pragma unroll
                for (int cc = 0; cc < 2; cc++) {
                    int j = n0 + wn + nt * 8 + 2 * t + cc;
                    float val = acc[mf][nt][rr * 2 + cc] + bias[j];
                    if (QKV) {
                        int b = m >> 11, l = m & 2047;
                        int ty = j >> 9, h = (j >> 6) & 7, d = j & 63;
                        float* dst = (ty == 0) ? g_q : (ty == 1) ? g_k : g_v;
                        dst[(((b * HH + h) * LL) + l) * DD + d] = val;
                    } else {
                        out[m * N + j] = val;
                    }
                }
            }
        }
    }
}

// ---------------- block means + min-cosine (Q and K fused in one launch) ----------------
__global__ void __launch_bounds__(128) block_meta_all() {
    __shared__ float tile[128 * 65];
    __shared__ float mean[64];
    __shared__ float red[128];
    __shared__ float nm_s;
    bool isq = blockIdx.x < BB * HH * NQ;
    int bid = isq ? blockIdx.x : blockIdx.x - BB * HH * NQ;
    int nb   = isq ? NQ : NK;
    int blk  = isq ? BLKQ : BLKK;
    const float* t = isq ? g_q : g_k;
    float* mout = isq ? g_qm : g_km;
    float* simout = isq ? g_qsim : g_ksim;
    int blkid = bid % nb;
    int bh = bid / nb;
    const float* base = t + (bh * LL + blkid * blk) * DD;
    int tid = threadIdx.x;
    for (int i = tid; i < blk * DD; i += 128) {
        int r = i >> 6, d = i & 63;
        tile[r * 65 + d] = base[i];
    }
    __syncthreads();
    if (tid < 64) {
        float s = 0.f;
        for (int r = 0; r < blk; r++) s += tile[r * 65 + tid];
        s *= (1.0f / blk);
        mean[tid] = s;
        mout[bid * 64 + tid] = s;
    }
    __syncthreads();
    if (tid == 0) {
        float s = 0.f;
        for (int d = 0; d < 64; d++) s += mean[d] * mean[d];
        nm_s = sqrtf(s) + 1e-6f;
    }
    __syncthreads();
    float mycos = CUDART_INF_F;
    if (tid < blk) {
        float dot = 0.f, nr = 0.f;
        for (int d = 0; d < 64; d++) {
            float xv = tile[tid * 65 + d];
            dot += xv * mean[d];
            nr += xv * xv;
        }
        mycos = dot / ((sqrtf(nr) + 1e-6f) * nm_s);
    }
    red[tid] = mycos;
    __syncthreads();
    for (int s = 64; s > 0; s >>= 1) {
        if (tid < s) red[tid] = fminf(red[tid], red[tid + s]);
        __syncthreads();
    }
    if (tid == 0) simout[bid] = red[0];
}

// ---------------- pooled softmax + CDF keep mask -> compacted kept-block lists ----------------
__global__ void __launch_bounds__(512) mask_kernel() {
    __shared__ float qm_s[NQ * DD];
    __shared__ float km_s[NK * DD];
    __shared__ float pooled[NQ][NK + 1];
    __shared__ float ksim_s[NK];
    int bh = blockIdx.x;
    int tid = threadIdx.x;
    for (int i = tid; i < NQ * DD; i += 512) qm_s[i] = g_qm[bh * NQ * DD + i];
    for (int i = tid; i < NK * DD; i += 512) km_s[i] = g_km[bh * NK * DD + i];
    if (tid < NK) ksim_s[tid] = g_ksim[bh * NK + tid];
    __syncthreads();
    {
        int qi = tid >> 5, j = tid & 31;
        const float* qv = &qm_s[qi * DD];
        const float* kv = &km_s[j * DD];
        float dot = 0.f;
        #pragma unroll
        for (int d = 0; d < DD; d++) dot += qv[d] * kv[d];
        pooled[qi][j] = dot * 0.125f;
    }
    __syncthreads();
    int w = tid >> 5;
    int lane = tid & 31;
    float v = pooled[w][lane];
    float mx = v;
    #pragma unroll
    for (int s = 16; s > 0; s >>= 1) mx = fmaxf(mx, __shfl_xor_sync(0xffffffffu, mx, s));
    float p = expf(v - mx);
    float sum = p;
    #pragma unroll
    for (int s = 16; s > 0; s >>= 1) sum += __shfl_xor_sync(0xffffffffu, sum, s);
    p /= sum;
    float sv = p;
    int si = lane;
    #pragma unroll
    for (int k = 2; k <= 32; k <<= 1) {
        #pragma unroll
        for (int j = k >> 1; j > 0; j >>= 1) {
            float ov = __shfl_xor_sync(0xffffffffu, sv, j);
            int   oi = __shfl_xor_sync(0xffffffffu, si, j);
            bool iprecede = (sv > ov) || (sv == ov && si < oi);
            bool lower = ((lane & j) == 0);
            bool dir = ((lane & k) == 0);
            bool keep_mine = ((lower == iprecede) == dir);
            if (!keep_mine) { sv = ov; si = oi; }
        }
    }
    float csum = sv;
    #pragma unroll
    for (int s = 1; s < 32; s <<= 1) {
        float t = __shfl_up_sync(0xffffffffu, csum, s);
        if (lane >= s) csum += t;
    }
    bool kept_sorted = (csum - sv) < 0.98f;
    unsigned keepmask = __reduce_or_sync(0xffffffffu, kept_sorted ? (1u << si) : 0u);
    bool qself = g_qsim[bh * NQ + w] > 0.6f;
    bool kself = ksim_s[lane] > 0.6f;
    bool fin = ((keepmask >> lane) & 1u) || !qself || !kself;
    unsigned fmask = __ballot_sync(0xffffffffu, fin);
    int pos = __popc(fmask & ((1u << lane) - 1u));
    int rowid = bh * NQ + w;
    if (fin) g_list[rowid * NK + pos] = lane;
    if (lane == 0) g_cnt[rowid] = __popc(fmask);
}

// ---------------- fp16 tensor-core flash attention (m16n8k16) ----------------
#define LDH 72
__global__ void __launch_bounds__(256) attn_kernel() {
    extern __shared__ __half smh[];
    __half* Ks = smh;               // [64 keys][LDH]
    __half* Vt = smh + 64 * LDH;    // [64 d][LDH]
    __half* Ps = smh + 128 * LDH;   // [128 q][LDH]

    int bh = blockIdx.y;
    int qb = blockIdx.x;
    int tid = threadIdx.x;
    int w = tid >> 5;
    int lane = tid & 31;
    int g = lane >> 2;
    int t = lane & 3;

    unsigned qa[4][4];
    {
        const float* q0 = g_q + (bh * LL + qb * 128 + w * 16 + g) * DD;
        const float* q1 = q0 + 8 * DD;
        #pragma unroll
        for (int kc = 0; kc < 4; kc++) {
            int c = kc * 16 + 2 * t;
            qa[kc][0] = pkh2(q0[c] * 0.125f,     q0[c + 1] * 0.125f);
            qa[kc][1] = pkh2(q1[c] * 0.125f,     q1[c + 1] * 0.125f);
            qa[kc][2] = pkh2(q0[c + 8] * 0.125f, q0[c + 9] * 0.125f);
            qa[kc][3] = pkh2(q1[c + 8] * 0.125f, q1[c + 9] * 0.125f);
        }
    }

    float oacc[8][4];
    #pragma unroll
    for (int dt = 0; dt < 8; dt++) { oacc[dt][0]=0.f; oacc[dt][1]=0.f; oacc[dt][2]=0.f; oacc[dt][3]=0.f; }
    float m0 = -CUDART_INF_F, m1 = -CUDART_INF_F;
    float l0 = 0.f, l1 = 0.f;

    int cnt = g_cnt[bh * NQ + qb];
    const int* __restrict__ list = g_list + (bh * NQ + qb) * NK;

    float4 pk[4], pv[4];
    if (cnt > 0) {
        int kb = list[0];
        const float4* Kg = (const float4*)(g_k + (bh * LL + kb * BLKK) * DD);
        const float4* Vg = (const float4*)(g_v + (bh * LL + kb * BLKK) * DD);
        #pragma unroll
        for (int i = 0; i < 4; i++) { pk[i] = Kg[tid + i * 256]; pv[i] = Vg[tid + i * 256]; }
    }

    for (int it = 0; it < cnt; it++) {
        __syncthreads();
        #pragma unroll
        for (int i = 0; i < 4; i++) {
            int idx = tid + i * 256;
            int row = idx >> 4, c4 = (idx & 15) * 4;
            float4 kv = pk[i];
            *(__half2*)&Ks[row * LDH + c4]     = __floats2half2_rn(kv.x, kv.y);
            *(__half2*)&Ks[row * LDH + c4 + 2] = __floats2half2_rn(kv.z, kv.w);
            float4 vv = pv[i];
            Vt[(c4 + 0) * LDH + row] = __float2half_rn(vv.x);
            Vt[(c4 + 1) * LDH + row] = __float2half_rn(vv.y);
            Vt[(c4 + 2) * LDH + row] = __float2half_rn(vv.z);
            Vt[(c4 + 3) * LDH + row] = __float2half_rn(vv.w);
        }
        __syncthreads();
        if (it + 1 < cnt) {
            int kb = list[it + 1];
            const float4* Kg = (const float4*)(g_k + (bh * LL + kb * BLKK) * DD);
            const float4* Vg = (const float4*)(g_v + (bh * LL + kb * BLKK) * DD);
            #pragma unroll
            for (int i = 0; i < 4; i++) { pk[i] = Kg[tid + i * 256]; pv[i] = Vg[tid + i * 256]; }
        }

        float sc[8][4];
        #pragma unroll
        for (int nt = 0; nt < 8; nt++) { sc[nt][0]=0.f; sc[nt][1]=0.f; sc[nt][2]=0.f; sc[nt][3]=0.f; }
        #pragma unroll
        for (int kc = 0; kc < 4; kc++) {
            #pragma unroll
            for (int nt = 0; nt < 8; nt++) {
                unsigned b0 = *(const unsigned*)&Ks[(nt * 8 + g) * LDH + kc * 16 + 2 * t];
                unsigned b1 = *(const unsigned*)&Ks[(nt * 8 + g) * LDH + kc * 16 + 2 * t + 8];
                MMA_F16(sc[nt], qa[kc][0], qa[kc][1], qa[kc][2], qa[kc][3], b0, b1);
            }
        }

        float mx0 = -CUDART_INF_F, mx1 = -CUDART_INF_F;
        #pragma unroll
        for (int nt = 0; nt < 8; nt++) {
            mx0 = fmaxf(mx0, fmaxf(sc[nt][0], sc[nt][1]));
            mx1 = fmaxf(mx1, fmaxf(sc[nt][2], sc[nt][3]));
        }
        mx0 = fmaxf(mx0, __shfl_xor_sync(0xffffffffu, mx0, 1));
        mx0 = fmaxf(mx0, __shfl_xor_sync(0xffffffffu, mx0, 2));
        mx1 = fmaxf(mx1, __shfl_xor_sync(0xffffffffu, mx1, 1));
        mx1 = fmaxf(mx1, __shfl_xor_sync(0xffffffffu, mx1, 2));
        float nm0 = fmaxf(m0, mx0);
        float nm1 = fmaxf(m1, mx1);
        float f0 = __expf(m0 - nm0);
        float f1 = __expf(m1 - nm1);
        #pragma unroll
        for (int dt = 0; dt < 8; dt++) {
            oacc[dt][0] *= f0; oacc[dt][1] *= f0;
            oacc[dt][2] *= f1; oacc[dt][3] *= f1;
        }
        l0 *= f0; l1 *= f1;
        m0 = nm0; m1 = nm1;

        float s0 = 0.f, s1 = 0.f;
        __half* p0 = &Ps[(w * 16 + g) * LDH];
        __half* p1 = &Ps[(w * 16 + g + 8) * LDH];
        #pragma unroll
        for (int nt = 0; nt < 8; nt++) {
            float e00 = __expf(sc[nt][0] - nm0);
            float e01 = __expf(sc[nt][1] - nm0);
            float e10 = __expf(sc[nt][2] - nm1);
            float e11 = __expf(sc[nt][3] - nm1);
            s0 += e00 + e01; s1 += e10 + e11;
            *(__half2*)&p0[nt * 8 + 2 * t] = __floats2half2_rn(e00, e01);
            *(__half2*)&p1[nt * 8 + 2 * t] = __floats2half2_rn(e10, e11);
        }
        s0 += __shfl_xor_sync(0xffffffffu, s0, 1);
        s0 += __shfl_xor_sync(0xffffffffu, s0, 2);
        s1 += __shfl_xor_sync(0xffffffffu, s1, 1);
        s1 += __shfl_xor_sync(0xffffffffu, s1, 2);
        l0 += s0; l1 += s1;
        __syncwarp();

        #pragma unroll
        for (int kc = 0; kc < 4; kc++) {
            unsigned a0 = *(const unsigned*)&Ps[(w * 16 + g) * LDH + kc * 16 + 2 * t];
            unsigned a1 = *(const unsigned*)&Ps[(w * 16 + g + 8) * LDH + kc * 16 + 2 * t];
            unsigned a2 = *(const unsigned*)&Ps[(w * 16 + g) * LDH + kc * 16 + 2 * t + 8];
            unsigned a3 = *(const unsigned*)&Ps[(w * 16 + g + 8) * LDH + kc * 16 + 2 * t + 8];
            #pragma unroll
            for (int dt = 0; dt < 8; dt++) {
                unsigned b0 = *(const unsigned*)&Vt[(dt * 8 + g) * LDH + kc * 16 + 2 * t];
                unsigned b1 = *(const unsigned*)&Vt[(dt * 8 + g) * LDH + kc * 16 + 2 * t + 8];
                MMA_F16(oacc[dt], a0, a1, a2, a3, b0, b1);
            }
        }
        __syncwarp();
    }

    float inv0 = 1.0f / l0;
    float inv1 = 1.0f / l1;
    int b = bh >> 3, h = bh & 7;
    int grow = qb * 128 + w * 16 + g;
    float* o0 = g_ot + (b * LL + grow) * CC + h * DD;
    float* o1 = o0 + 8 * CC;
    #pragma unroll
    for (int dt = 0; dt < 8; dt++) {
        *(float2*)&o0[dt * 8 + 2 * t] = make_float2(oacc[dt][0] * inv0, oacc[dt][1] * inv0);
        *(float2*)&o1[dt * 8 + 2 * t] = make_float2(oacc[dt][2] * inv1, oacc[dt][3] * inv1);
    }
}

extern "C" void kernel_launch(void* const* d_in, const int* in_sizes, int n_in,
                              void* d_out, int out_size) {
    const float* x     = (const float*)d_in[0];
    const float* Wqkv  = (const float*)d_in[1];
    const float* bqkv  = (const float*)d_in[2];
    const float* Wproj = (const float*)d_in[3];
    const float* bproj = (const float*)d_in[4];
    float* out = (float*)d_out;

    cudaFuncSetAttribute(gemm_f16<3 * CC, true>, cudaFuncAttributeMaxDynamicSharedMemorySize, GSMEM);
    cudaFuncSetAttribute(gemm_f16<CC, false>, cudaFuncAttributeMaxDynamicSharedMemorySize, GSMEM);

    dim3 g1(12, 32);                       // N=1536/128, M=4096/128
    gemm_f16<3 * CC, true><<<g1, 256, GSMEM>>>(x, Wqkv, bqkv, nullptr);

    block_meta_all<<<BB * HH * (NQ + NK), 128>>>();

    mask_kernel<<<BB * HH, 512>>>();

    const int smem = 256 * LDH * sizeof(__half);   // 36864 B
    cudaFuncSetAttribute(attn_kernel, cudaFuncAttributeMaxDynamicSharedMemorySize, smem);
    dim3 ga(NQ, BB * HH);
    attn_kernel<<<ga, 256, smem>>>();

    dim3 g2(4, 32);                        // N=512/128, M=4096/128
    gemm_f16<CC, false><<<g2, 256, GSMEM>>>(nullptr, Wproj, bproj, out);
}